// round 9
// baseline (speedup 1.0000x reference)
#include <cuda_runtime.h>
#include <cstdint>

#define BATCH 4
#define NVOX  32768
#define NROWS (BATCH*NVOX)
#define C     128
#define NCLS  10
#define TOPK  500
#define NCHUNK 4
#define CHUNK  (NVOX/NCHUNK)          // 8192
#define CAND_PER_B (NCLS*NCHUNK*TOPK) // 20000
#define GD_BATCH 8

// hm mma.sync config
#define HM_GRID 148
#define NTILES  (NROWS/128)           // 1024
#define XPAD 132
// dynamic smem layout in floats
#define SM_XS  0                      // [128][132] X tile
#define SM_WP  (128*XPAD)             // 16896: packed W fragments [16][16][32][4]
#define SM_W2  (SM_WP + 32768)        // 49664: [128][10]
#define SM_BF  (SM_W2 + C*NCLS)       // 50944: [128]
#define SM_PO  (SM_BF + 128)          // 51072: [4][128][10] (also inv[] during prologue)
#define SM_FLOATS (SM_PO + 5120)      // 56192 -> 224768 bytes

// ---------------- device scratch ----------------
__device__ float g_hm[BATCH*NCLS*NVOX];            // raw logits
__device__ float g_cand_score[BATCH*CAND_PER_B];
__device__ int   g_cand_vox[BATCH*CAND_PER_B];
__device__ float g_sel_score[BATCH*TOPK];
__device__ int   g_sel_cls[BATCH*TOPK];
__device__ int   g_sel_vox[BATCH*TOPK];

__device__ __forceinline__ uint32_t f2tf32(float x) {
    uint32_t u;
    asm("cvt.rna.tf32.f32 %0, %1;" : "=r"(u) : "f"(x));
    return u;
}
__device__ __forceinline__ void mma_tf32(float* d, const uint32_t* a, const uint32_t* b) {
    asm volatile("mma.sync.aligned.m16n8k8.row.col.f32.tf32.tf32.f32 "
        "{%0,%1,%2,%3}, {%4,%5,%6,%7}, {%8,%9}, {%0,%1,%2,%3};"
        : "+f"(d[0]), "+f"(d[1]), "+f"(d[2]), "+f"(d[3])
        : "r"(a[0]), "r"(a[1]), "r"(a[2]), "r"(a[3]), "r"(b[0]), "r"(b[1]));
}

// ---------------- kernel 1: dense hm head, TF32 mma.sync 3-term split ----------------
// 512 threads = 16 warps in 4x4 grid; warp tile 32 rows x 32 cols.
// Prologue folds BN into W0 and packs tf32 hi/lo fragments in smem (no fold kernel).
__global__ void __launch_bounds__(512, 1)
hm_kernel(const float* __restrict__ feats,
          const float* __restrict__ W1, const float* __restrict__ b1,
          const float* __restrict__ gam, const float* __restrict__ bet,
          const float* __restrict__ mu,  const float* __restrict__ var,
          const float* __restrict__ W2, const float* __restrict__ b2) {
    extern __shared__ float sm[];
    float*  Xs  = sm + SM_XS;
    float*  Wp  = sm + SM_WP;
    float4* Wp4 = reinterpret_cast<float4*>(Wp);
    float*  W2s = sm + SM_W2;
    float*  bfs = sm + SM_BF;
    float*  po2 = sm + SM_PO;              // [4][128][10]; inv[] during prologue

    int tid  = threadIdx.x;
    int wid  = tid >> 5;
    int lane = tid & 31;
    int wm = wid >> 2, wn = wid & 3;       // warp tile: rows wm*32, cols wn*32

    // ---- prologue: fold BN for head 0, pack fragments ----
    if (tid < C) {
        float inv = gam[tid] / sqrtf(var[tid] + 1e-5f);
        po2[tid] = inv;                                     // temp inv[]
        bfs[tid] = (b1[tid] - mu[tid]) * inv + bet[tid];
    }
    for (int i = tid; i < C*NCLS; i += 512) W2s[i] = W2[i];
    __syncthreads();
    for (int i = tid; i < C*C; i += 512) {
        int k = i >> 7, c = i & 127;
        float val = W1[i] * po2[c];
        float hi = __uint_as_float(f2tf32(val));
        float lo = __uint_as_float(f2tf32(val - hi));
        int ks   = k >> 3;
        int kk   = k & 7;
        int klo2 = kk & 3;
        int half = kk >> 2;
        int ln   = ((c & 7) << 2) | klo2;
        int nt   = c >> 3;
        int base = (((ks*16) + nt)*32 + ln)*4;
        Wp[base + half]     = hi;
        Wp[base + 2 + half] = lo;
    }
    float b2r[NCLS];
    #pragma unroll
    for (int j = 0; j < NCLS; j++) b2r[j] = __ldg(b2 + j);
    __syncthreads();

    for (int tile = blockIdx.x; tile < NTILES; tile += HM_GRID) {
        int row0 = tile * 128;

        // load X tile row-major
        for (int t = tid; t < 128*32; t += 512) {
            int r  = t >> 5;
            int c4 = (t & 31) << 2;
            float4 f = *reinterpret_cast<const float4*>(feats + (long)(row0 + r)*C + c4);
            *reinterpret_cast<float4*>(Xs + r*XPAD + c4) = f;
        }
        __syncthreads();

        float acc[2][4][4];
        #pragma unroll
        for (int mi = 0; mi < 2; mi++)
            #pragma unroll
            for (int ni = 0; ni < 4; ni++)
                #pragma unroll
                for (int q = 0; q < 4; q++) acc[mi][ni][q] = 0.f;

        int arow = wm*32 + (lane >> 2);
        int klo  = lane & 3;

        #pragma unroll 4
        for (int ks = 0; ks < 16; ks++) {
            int k0 = ks * 8;
            uint32_t ahi[2][4], alo[2][4];
            #pragma unroll
            for (int mi = 0; mi < 2; mi++) {
                int rb = arow + mi*16;
                #pragma unroll
                for (int j = 0; j < 4; j++) {
                    int r = rb + (j & 1)*8;
                    int k = k0 + klo + (j >> 1)*4;
                    float x = Xs[r*XPAD + k];
                    uint32_t h = f2tf32(x);
                    ahi[mi][j] = h;
                    alo[mi][j] = f2tf32(x - __uint_as_float(h));
                }
            }
            #pragma unroll
            for (int ni = 0; ni < 4; ni++) {
                int nt = wn*4 + ni;
                float4 v = Wp4[(ks*16 + nt)*32 + lane];
                uint32_t bh[2] = {__float_as_uint(v.x), __float_as_uint(v.y)};
                uint32_t bl[2] = {__float_as_uint(v.z), __float_as_uint(v.w)};
                #pragma unroll
                for (int mi = 0; mi < 2; mi++) {
                    mma_tf32(acc[mi][ni], ahi[mi], bh);
                    mma_tf32(acc[mi][ni], ahi[mi], bl);
                    mma_tf32(acc[mi][ni], alo[mi], bh);
                }
            }
        }

        // ---- epilogue directly from accumulators ----
        float po[4][NCLS];
        #pragma unroll
        for (int s = 0; s < 4; s++)
            #pragma unroll
            for (int j = 0; j < NCLS; j++) po[s][j] = 0.f;

        #pragma unroll
        for (int ni = 0; ni < 4; ni++) {
            #pragma unroll
            for (int t = 0; t < 2; t++) {
                int c = wn*32 + ni*8 + 2*(lane & 3) + t;
                float bfc = bfs[c];
                float w2l[NCLS];
                #pragma unroll
                for (int j = 0; j < NCLS; j++) w2l[j] = W2s[c*NCLS + j];
                #pragma unroll
                for (int mi = 0; mi < 2; mi++) {
                    float h0 = fmaxf(acc[mi][ni][t]     + bfc, 0.f);
                    float h1 = fmaxf(acc[mi][ni][t + 2] + bfc, 0.f);
                    #pragma unroll
                    for (int j = 0; j < NCLS; j++) {
                        po[mi*2 + 0][j] += h0 * w2l[j];
                        po[mi*2 + 1][j] += h1 * w2l[j];
                    }
                }
            }
        }
        #pragma unroll
        for (int s = 0; s < 4; s++)
            #pragma unroll
            for (int j = 0; j < NCLS; j++) {
                float v = po[s][j];
                v += __shfl_xor_sync(0xffffffff, v, 1);
                v += __shfl_xor_sync(0xffffffff, v, 2);
                po[s][j] = v;
            }
        if ((lane & 3) == 0) {
            int rbase = wm*32 + (lane >> 2);
            #pragma unroll
            for (int s = 0; s < 4; s++) {
                int row = rbase + ((s & 1) ? 8 : 0) + ((s >> 1) ? 16 : 0);
                #pragma unroll
                for (int j = 0; j < NCLS; j++)
                    po2[(wn*128 + row)*NCLS + j] = po[s][j];
            }
        }
        __syncthreads();

        // final: sum 4 quarters + bias, store RAW logits (first 256 threads)
        if (tid < 256) {
            int row = tid >> 1;
            int j0  = (tid & 1) * 5;
            int rrow = row0 + row;
            int b    = rrow >> 15;
            int v    = rrow & (NVOX - 1);
            #pragma unroll
            for (int j = 0; j < 5; j++) {
                float val = po2[row*NCLS + j0 + j] + po2[(128 + row)*NCLS + j0 + j]
                          + po2[(256 + row)*NCLS + j0 + j] + po2[(384 + row)*NCLS + j0 + j]
                          + b2r[j0 + j];
                g_hm[((long)(b*NCLS + j0 + j))*NVOX + v] = val;
            }
        }
        __syncthreads();   // Xs + po2 free for next tile
    }
}

// ---------------- radix helpers ----------------
__device__ __forceinline__ unsigned key_of(float f) {
    unsigned u = __float_as_uint(f);
    return (u & 0x80000000u) ? ~u : (u | 0x80000000u);
}
__device__ __forceinline__ float float_of(unsigned k) {
    unsigned u = (k & 0x80000000u) ? (k & 0x7FFFFFFFu) : ~k;
    return __uint_as_float(u);
}
__device__ __forceinline__ void hist_add(int* hist, unsigned bin, bool act) {
    unsigned lm = __activemask();
    unsigned amask = __ballot_sync(lm, act);
    if (act) {
        unsigned peers = __match_any_sync(amask, bin);
        int leader = __ffs(peers) - 1;
        if ((int)(threadIdx.x & 31) == leader)
            atomicAdd(&hist[bin], __popc(peers));
    }
}
__device__ __forceinline__ void pick_bucket(int* hist, unsigned* sh_prefix,
                                            int* sh_rem, int shift) {
    __syncthreads();
    if (threadIdx.x < 32) {
        int lane = threadIdx.x;
        int b0 = lane * 8;
        int loc[8];
        int tot = 0;
        #pragma unroll
        for (int q = 0; q < 8; q++) { loc[q] = hist[b0 + q]; tot += loc[q]; }
        int s = tot;
        #pragma unroll
        for (int off = 1; off < 32; off <<= 1) {
            int t = __shfl_down_sync(0xffffffff, s, off);
            if (lane + off < 32) s += t;
        }
        int rem = *sh_rem;
        int cum = s - tot;
        #pragma unroll
        for (int q = 7; q >= 0; q--) {
            int prev = cum;
            cum += loc[q];
            if (cum >= rem && prev < rem) {
                *sh_rem    = rem - prev;
                *sh_prefix = *sh_prefix | ((unsigned)(b0 + q) << shift);
            }
        }
    }
    __syncthreads();
}
__constant__ unsigned c_mask[4] = {0u, 0xFF000000u, 0xFFFF0000u, 0xFFFFFF00u};

// ---------------- kernel 2: per-(b,cls,chunk) local top-500 ----------------
__global__ void __launch_bounds__(512)
topk_chunk_kernel() {
    __shared__ unsigned skey[CHUNK];
    __shared__ int hist[256];
    __shared__ unsigned sh_prefix;
    __shared__ int sh_rem, cgt, ceq;

    int blk = blockIdx.x;
    int bc  = blk >> 2, chunk = blk & 3;
    int tid = threadIdx.x, nt = blockDim.x;
    const float* src = g_hm + (long)bc * NVOX + chunk * CHUNK;

    for (int v = tid; v < CHUNK; v += nt) skey[v] = key_of(src[v]);
    if (tid == 0) { sh_prefix = 0; sh_rem = TOPK; }
    if (tid < 256) hist[tid] = 0;
    __syncthreads();

    #pragma unroll
    for (int p = 0; p < 4; p++) {
        int shift = 24 - 8*p;
        unsigned mask = c_mask[p], pref = sh_prefix;
        for (int v = tid; v < CHUNK; v += nt) {
            unsigned k = skey[v];
            hist_add(hist, (k >> shift) & 0xFF, (k & mask) == pref);
        }
        pick_bucket(hist, &sh_prefix, &sh_rem, shift);
        if (tid < 256) hist[tid] = 0;
        if (p == 3 && tid == 0) { cgt = 0; ceq = 0; }
        __syncthreads();
    }
    unsigned T = sh_prefix;
    int nEq = sh_rem;
    int nGt = TOPK - nEq;

    float* outS = g_cand_score + blk * TOPK;
    int*   outV = g_cand_vox   + blk * TOPK;
    int voff = chunk * CHUNK;
    for (int v = tid; v < CHUNK; v += nt) {
        unsigned k = skey[v];
        int slot = -1;
        if (k > T)       slot = atomicAdd(&cgt, 1);
        else if (k == T) { int q = atomicAdd(&ceq, 1); if (q < nEq) slot = nGt + q; }
        if (slot >= 0) { outS[slot] = src[v]; outV[slot] = voff + v; }
    }
}

// ---------------- kernel 3: per-batch top-500 of 20000 (rank-by-count) ----------------
__global__ void global_topk_kernel() {
    extern __shared__ unsigned sm3[];
    unsigned* skey = sm3;                                                // [20000]
    unsigned long long* sortb = (unsigned long long*)(sm3 + CAND_PER_B); // [512]
    __shared__ int hist[256];
    __shared__ unsigned sh_prefix;
    __shared__ int sh_rem, cgt, ceq;

    int b = blockIdx.x, tid = threadIdx.x, nt = blockDim.x;
    const float* cs = g_cand_score + (long)b * CAND_PER_B;

    for (int i = tid; i < CAND_PER_B; i += nt) skey[i] = key_of(cs[i]);
    if (tid < 512) sortb[tid] = 0ull;
    if (tid == 0) { sh_prefix = 0; sh_rem = TOPK; }
    if (tid < 256) hist[tid] = 0;
    __syncthreads();

    #pragma unroll
    for (int p = 0; p < 4; p++) {
        int shift = 24 - 8*p;
        unsigned mask = c_mask[p], pref = sh_prefix;
        for (int i = tid; i < CAND_PER_B; i += nt) {
            unsigned k = skey[i];
            hist_add(hist, (k >> shift) & 0xFF, (k & mask) == pref);
        }
        pick_bucket(hist, &sh_prefix, &sh_rem, shift);
        if (tid < 256) hist[tid] = 0;
        if (p == 3 && tid == 0) { cgt = 0; ceq = 0; }
        __syncthreads();
    }
    unsigned T = sh_prefix;
    int nEq = sh_rem;
    int nGt = TOPK - nEq;

    for (int i = tid; i < CAND_PER_B; i += nt) {
        unsigned k = skey[i];
        int slot = -1;
        if (k > T)       slot = atomicAdd(&cgt, 1);
        else if (k == T) { int q = atomicAdd(&ceq, 1); if (q < nEq) slot = nGt + q; }
        if (slot >= 0)
            sortb[slot] = (((unsigned long long)k) << 32) | (unsigned)i;
    }
    __syncthreads();

    if (tid < 512) {
        unsigned long long mine = sortb[tid];
        int rank = 0;
        for (int j = 0; j < 512; j++)
            rank += (sortb[j] > mine);
        if (mine != 0ull && rank < TOPK) {
            int idx = (int)(mine & 0xFFFFFFFFu);
            g_sel_score[b*TOPK + rank] = float_of((unsigned)(mine >> 32));
            g_sel_cls  [b*TOPK + rank] = idx / (NCHUNK*TOPK);
            g_sel_vox  [b*TOPK + rank] = g_cand_vox[(long)b*CAND_PER_B + idx];
        }
    }
}

// ---------------- kernel 4: 5 small heads in PARALLEL + decode (BN folded on the fly) ----------------
__global__ void __launch_bounds__(640)
gather_decode_kernel(const float* __restrict__ feats, const int* __restrict__ voxel_xy,
                     const float* __restrict__ W1, const float* __restrict__ b1,
                     const float* __restrict__ gam, const float* __restrict__ bet,
                     const float* __restrict__ mu,  const float* __restrict__ var,
                     const float* __restrict__ W2c, const float* __restrict__ b2c,
                     const float* __restrict__ W2z, const float* __restrict__ b2z,
                     const float* __restrict__ W2d, const float* __restrict__ b2d,
                     const float* __restrict__ W2r, const float* __restrict__ b2r,
                     const float* __restrict__ W2v, const float* __restrict__ b2v,
                     float* __restrict__ out) {
    int e0  = blockIdx.x * GD_BATCH;
    int tid = threadIdx.x;
    int hh  = tid >> 7;            // head group 0..4
    int wt  = tid & 127;
    __shared__ float xr[GD_BATCH][C];
    __shared__ float hs[5][GD_BATCH][C];
    __shared__ float res[GD_BATCH][10];
    __shared__ int   svox[GD_BATCH];

    if (tid < GD_BATCH) svox[tid] = g_sel_vox[e0 + tid];
    __syncthreads();

    for (int i = tid; i < GD_BATCH*C; i += 640) {
        int c = i >> 7, k = i & 127;
        int e = e0 + c;
        int row = (e / TOPK) * NVOX + svox[c];
        xr[c][k] = feats[(long)row*C + k];
    }
    __syncthreads();

    const float* w2; const float* bp2; int oc, sb;
    if      (hh == 0) { w2 = W2c; bp2 = b2c; oc = 2; sb = 0; }
    else if (hh == 1) { w2 = W2z; bp2 = b2z; oc = 1; sb = 2; }
    else if (hh == 2) { w2 = W2d; bp2 = b2d; oc = 3; sb = 3; }
    else if (hh == 3) { w2 = W2r; bp2 = b2r; oc = 2; sb = 6; }
    else              { w2 = W2v; bp2 = b2v; oc = 2; sb = 8; }

    {
        int h = hh + 1;
        int hc = h*C + wt;
        float inv = gam[hc] / sqrtf(var[hc] + 1e-5f);
        float bb  = (b1[hc] - mu[hc]) * inv + bet[hc];
        const float* w = W1 + h*C*C + wt;          // raw weights; fold via inv at end
        float acc[GD_BATCH];
        #pragma unroll
        for (int c = 0; c < GD_BATCH; c++) acc[c] = 0.f;
        #pragma unroll 4
        for (int kk = 0; kk < C; kk++) {
            float wv = w[kk*C];
            #pragma unroll
            for (int c = 0; c < GD_BATCH; c++) acc[c] += xr[c][kk] * wv;
        }
        #pragma unroll
        for (int c = 0; c < GD_BATCH; c++) hs[hh][c][wt] = fmaxf(acc[c]*inv + bb, 0.f);
    }
    __syncthreads();

    {
        int cand = wt >> 4, col = wt & 15;
        if (col < oc) {
            float a2 = __ldg(bp2 + col);
            for (int kk = 0; kk < C; kk++) a2 += hs[hh][cand][kk] * __ldg(w2 + kk*oc + col);
            res[cand][sb + col] = (hh == 2) ? expf(a2) : a2;
        }
    }
    __syncthreads();

    if (tid < GD_BATCH) {
        int e = e0 + tid;
        int b = e / TOPK, k = e % TOPK;
        float score = 1.f / (1.f + expf(-g_sel_score[e]));
        int   cls   = g_sel_cls[e];
        int   vox   = svox[tid];
        int   row   = b * NVOX + vox;
        float vx = (float)voxel_xy[row*2 + 0];
        float vy = (float)voxel_xy[row*2 + 1];
        float xs = (vx + res[tid][0]) * 0.6f - 54.0f;
        float ys = (vy + res[tid][1]) * 0.6f - 54.0f;
        float cz = res[tid][2];
        float ang = atan2f(res[tid][7], res[tid][6]);
        bool m = (xs >= -61.2f) && (xs <= 61.2f) &&
                 (ys >= -61.2f) && (ys <= 61.2f) &&
                 (cz >= -10.f)  && (cz <= 10.f)  && (score > 0.1f);
        float mf = m ? 1.f : 0.f;
        float* ob = out + (long)(b*TOPK + k) * 10;
        ob[0] = xs * mf;  ob[1] = ys * mf;  ob[2] = cz * mf;
        ob[3] = res[tid][3] * mf; ob[4] = res[tid][4] * mf; ob[5] = res[tid][5] * mf;
        ob[6] = ang * mf; ob[7] = res[tid][8] * mf; ob[8] = res[tid][9] * mf;
        ob[9] = score * mf;
        int base = b*TOPK + k;
        out[BATCH*TOPK*10                 + base] = m ? (float)(cls + 1) : 0.f;
        out[BATCH*TOPK*10 + BATCH*TOPK   + base] = (float)(vox + b*NVOX);
        out[BATCH*TOPK*10 + 2*BATCH*TOPK + base] = mf;
    }
}

// ---------------- host launcher ----------------
extern "C" void kernel_launch(void* const* d_in, const int* in_sizes, int n_in,
                              void* d_out, int out_size) {
    const float* feats    = (const float*)d_in[0];
    const int*   voxel_xy = (const int*)d_in[1];
    const float* W1  = (const float*)d_in[2];
    const float* b1  = (const float*)d_in[3];
    const float* gam = (const float*)d_in[4];
    const float* bet = (const float*)d_in[5];
    const float* mu  = (const float*)d_in[6];
    const float* var = (const float*)d_in[7];
    const float* W2_hm = (const float*)d_in[8];
    const float* b2_hm = (const float*)d_in[9];
    const float* W2_c  = (const float*)d_in[10];
    const float* b2_c  = (const float*)d_in[11];
    const float* W2_z  = (const float*)d_in[12];
    const float* b2_z  = (const float*)d_in[13];
    const float* W2_d  = (const float*)d_in[14];
    const float* b2_d  = (const float*)d_in[15];
    const float* W2_r  = (const float*)d_in[16];
    const float* b2_r  = (const float*)d_in[17];
    const float* W2_v  = (const float*)d_in[18];
    const float* b2_v  = (const float*)d_in[19];
    float* out = (float*)d_out;

    const int smem1 = SM_FLOATS * (int)sizeof(float);                 // 224768 B
    const int smem3 = CAND_PER_B * (int)sizeof(unsigned) + 512 * 8;
    cudaFuncSetAttribute(hm_kernel,          cudaFuncAttributeMaxDynamicSharedMemorySize, smem1);
    cudaFuncSetAttribute(global_topk_kernel, cudaFuncAttributeMaxDynamicSharedMemorySize, smem3);

    hm_kernel<<<HM_GRID, 512, smem1>>>(feats, W1, b1, gam, bet, mu, var, W2_hm, b2_hm);
    topk_chunk_kernel<<<BATCH * NCLS * NCHUNK, 512>>>();
    global_topk_kernel<<<BATCH, 1024, smem3>>>();
    gather_decode_kernel<<<BATCH * TOPK / GD_BATCH, 640>>>(feats, voxel_xy,
                                                W1, b1, gam, bet, mu, var,
                                                W2_c, b2_c, W2_z, b2_z, W2_d, b2_d,
                                                W2_r, b2_r, W2_v, b2_v, out);
}

// round 10
// speedup vs baseline: 1.0089x; 1.0089x over previous
#include <cuda_runtime.h>
#include <cstdint>

#define BATCH 4
#define NVOX  32768
#define NROWS (BATCH*NVOX)
#define C     128
#define NCLS  10
#define TOPK  500
#define NCHUNK 4
#define CHUNK  (NVOX/NCHUNK)          // 8192
#define CAND_PER_B (NCLS*NCHUNK*TOPK) // 20000
#define GD_BATCH 8

// hm mma.sync config (R8 shape: 256 threads, 8 warps 4x2)
#define HM_GRID 148
#define NTILES  (NROWS/128)           // 1024
#define XPAD 132
#define SM_XS  0                      // [128][132] X tile
#define SM_WP  (128*XPAD)             // 16896: packed W fragments [16][16][32][4]
#define SM_W2  (SM_WP + 32768)        // 49664: [128][10]
#define SM_BF  (SM_W2 + C*NCLS)       // 50944: [128]
#define SM_PO  (SM_BF + 128)          // 51072: [2][128][10] (inv[] during prologue)
#define SM_FLOATS (SM_PO + 2560)      // 53632 -> 214528 bytes

// ---------------- device scratch ----------------
__device__ float g_hm[BATCH*NCLS*NVOX];            // raw logits
__device__ float g_cand_score[BATCH*CAND_PER_B];
__device__ int   g_cand_vox[BATCH*CAND_PER_B];
__device__ float g_sel_score[BATCH*TOPK];
__device__ int   g_sel_cls[BATCH*TOPK];
__device__ int   g_sel_vox[BATCH*TOPK];

__device__ __forceinline__ uint32_t f2tf32(float x) {
    uint32_t u;
    asm("cvt.rna.tf32.f32 %0, %1;" : "=r"(u) : "f"(x));
    return u;
}
__device__ __forceinline__ void mma_tf32(float* d, const uint32_t* a, const uint32_t* b) {
    asm volatile("mma.sync.aligned.m16n8k8.row.col.f32.tf32.tf32.f32 "
        "{%0,%1,%2,%3}, {%4,%5,%6,%7}, {%8,%9}, {%0,%1,%2,%3};"
        : "+f"(d[0]), "+f"(d[1]), "+f"(d[2]), "+f"(d[3])
        : "r"(a[0]), "r"(a[1]), "r"(a[2]), "r"(a[3]), "r"(b[0]), "r"(b[1]));
}

// ---------------- kernel 1: dense hm head, TF32 mma.sync 3-term split ----------------
// 256 threads / 8 warps (4x2); prologue folds BN + packs fragments (no fold kernel).
__global__ void __launch_bounds__(256, 1)
hm_kernel(const float* __restrict__ feats,
          const float* __restrict__ W1, const float* __restrict__ b1,
          const float* __restrict__ gam, const float* __restrict__ bet,
          const float* __restrict__ mu,  const float* __restrict__ var,
          const float* __restrict__ W2, const float* __restrict__ b2) {
    extern __shared__ float sm[];
    float*  Xs  = sm + SM_XS;
    float*  Wp  = sm + SM_WP;
    float4* Wp4 = reinterpret_cast<float4*>(Wp);
    float*  W2s = sm + SM_W2;
    float*  bfs = sm + SM_BF;
    float*  po2 = sm + SM_PO;              // [2][128][10]; inv[] during prologue

    int tid  = threadIdx.x;
    int wid  = tid >> 5;
    int lane = tid & 31;
    int wm = wid >> 1, wn = wid & 1;       // warp tile: rows wm*32, cols wn*64

    // ---- prologue: fold BN for head 0, pack fragments ----
    if (tid < C) {
        float inv = gam[tid] / sqrtf(var[tid] + 1e-5f);
        po2[tid] = inv;
        bfs[tid] = (b1[tid] - mu[tid]) * inv + bet[tid];
    }
    for (int i = tid; i < C*NCLS; i += 256) W2s[i] = W2[i];
    __syncthreads();
    for (int i = tid; i < C*C; i += 256) {
        int k = i >> 7, c = i & 127;
        float val = W1[i] * po2[c];
        float hi = __uint_as_float(f2tf32(val));
        float lo = __uint_as_float(f2tf32(val - hi));
        int ks   = k >> 3;
        int kk   = k & 7;
        int klo2 = kk & 3;
        int half = kk >> 2;
        int ln   = ((c & 7) << 2) | klo2;
        int nt   = c >> 3;
        int base = (((ks*16) + nt)*32 + ln)*4;
        Wp[base + half]     = hi;
        Wp[base + 2 + half] = lo;
    }
    float b2r[NCLS];
    #pragma unroll
    for (int j = 0; j < NCLS; j++) b2r[j] = __ldg(b2 + j);
    __syncthreads();

    for (int tile = blockIdx.x; tile < NTILES; tile += HM_GRID) {
        int row0 = tile * 128;

        for (int t = tid; t < 128*32; t += 256) {
            int r  = t >> 5;
            int c4 = (t & 31) << 2;
            float4 f = *reinterpret_cast<const float4*>(feats + (long)(row0 + r)*C + c4);
            *reinterpret_cast<float4*>(Xs + r*XPAD + c4) = f;
        }
        __syncthreads();

        float acc[2][8][4];
        #pragma unroll
        for (int mi = 0; mi < 2; mi++)
            #pragma unroll
            for (int ni = 0; ni < 8; ni++)
                #pragma unroll
                for (int q = 0; q < 4; q++) acc[mi][ni][q] = 0.f;

        int arow = wm*32 + (lane >> 2);
        int klo  = lane & 3;

        #pragma unroll 4
        for (int ks = 0; ks < 16; ks++) {
            int k0 = ks * 8;
            uint32_t ahi[2][4], alo[2][4];
            #pragma unroll
            for (int mi = 0; mi < 2; mi++) {
                int rb = arow + mi*16;
                #pragma unroll
                for (int j = 0; j < 4; j++) {
                    int r = rb + (j & 1)*8;
                    int k = k0 + klo + (j >> 1)*4;
                    float x = Xs[r*XPAD + k];
                    uint32_t h = f2tf32(x);
                    ahi[mi][j] = h;
                    alo[mi][j] = f2tf32(x - __uint_as_float(h));
                }
            }
            #pragma unroll
            for (int ni = 0; ni < 8; ni++) {
                int nt = wn*8 + ni;
                float4 v = Wp4[(ks*16 + nt)*32 + lane];
                uint32_t bh[2] = {__float_as_uint(v.x), __float_as_uint(v.y)};
                uint32_t bl[2] = {__float_as_uint(v.z), __float_as_uint(v.w)};
                #pragma unroll
                for (int mi = 0; mi < 2; mi++) {
                    mma_tf32(acc[mi][ni], ahi[mi], bh);
                    mma_tf32(acc[mi][ni], ahi[mi], bl);
                    mma_tf32(acc[mi][ni], alo[mi], bh);
                }
            }
        }

        // ---- epilogue directly from accumulators ----
        float po[4][NCLS];
        #pragma unroll
        for (int s = 0; s < 4; s++)
            #pragma unroll
            for (int j = 0; j < NCLS; j++) po[s][j] = 0.f;

        #pragma unroll
        for (int ni = 0; ni < 8; ni++) {
            #pragma unroll
            for (int t = 0; t < 2; t++) {
                int c = wn*64 + ni*8 + 2*(lane & 3) + t;
                float bfc = bfs[c];
                float w2l[NCLS];
                #pragma unroll
                for (int j = 0; j < NCLS; j++) w2l[j] = W2s[c*NCLS + j];
                #pragma unroll
                for (int mi = 0; mi < 2; mi++) {
                    float h0 = fmaxf(acc[mi][ni][t]     + bfc, 0.f);
                    float h1 = fmaxf(acc[mi][ni][t + 2] + bfc, 0.f);
                    #pragma unroll
                    for (int j = 0; j < NCLS; j++) {
                        po[mi*2 + 0][j] += h0 * w2l[j];
                        po[mi*2 + 1][j] += h1 * w2l[j];
                    }
                }
            }
        }
        #pragma unroll
        for (int s = 0; s < 4; s++)
            #pragma unroll
            for (int j = 0; j < NCLS; j++) {
                float v = po[s][j];
                v += __shfl_xor_sync(0xffffffff, v, 1);
                v += __shfl_xor_sync(0xffffffff, v, 2);
                po[s][j] = v;
            }
        if ((lane & 3) == 0) {
            int rbase = wm*32 + (lane >> 2);
            #pragma unroll
            for (int s = 0; s < 4; s++) {
                int row = rbase + ((s & 1) ? 8 : 0) + ((s >> 1) ? 16 : 0);
                #pragma unroll
                for (int j = 0; j < NCLS; j++)
                    po2[(wn*128 + row)*NCLS + j] = po[s][j];
            }
        }
        __syncthreads();

        {
            int row = tid >> 1;
            int j0  = (tid & 1) * 5;
            int rrow = row0 + row;
            int b    = rrow >> 15;
            int v    = rrow & (NVOX - 1);
            #pragma unroll
            for (int j = 0; j < 5; j++) {
                float val = po2[row*NCLS + j0 + j] + po2[(128 + row)*NCLS + j0 + j] + b2r[j0 + j];
                g_hm[((long)(b*NCLS + j0 + j))*NVOX + v] = val;
            }
        }
        __syncthreads();
    }
}

// ---------------- radix helpers ----------------
__device__ __forceinline__ unsigned key_of(float f) {
    unsigned u = __float_as_uint(f);
    return (u & 0x80000000u) ? ~u : (u | 0x80000000u);
}
__device__ __forceinline__ float float_of(unsigned k) {
    unsigned u = (k & 0x80000000u) ? (k & 0x7FFFFFFFu) : ~k;
    return __uint_as_float(u);
}
__device__ __forceinline__ void hist_add(int* hist, unsigned bin, bool act) {
    unsigned lm = __activemask();
    unsigned amask = __ballot_sync(lm, act);
    if (act) {
        unsigned peers = __match_any_sync(amask, bin);
        int leader = __ffs(peers) - 1;
        if ((int)(threadIdx.x & 31) == leader)
            atomicAdd(&hist[bin], __popc(peers));
    }
}
__device__ __forceinline__ void pick_bucket(int* hist, unsigned* sh_prefix,
                                            int* sh_rem, int shift) {
    __syncthreads();
    if (threadIdx.x < 32) {
        int lane = threadIdx.x;
        int b0 = lane * 8;
        int loc[8];
        int tot = 0;
        #pragma unroll
        for (int q = 0; q < 8; q++) { loc[q] = hist[b0 + q]; tot += loc[q]; }
        int s = tot;
        #pragma unroll
        for (int off = 1; off < 32; off <<= 1) {
            int t = __shfl_down_sync(0xffffffff, s, off);
            if (lane + off < 32) s += t;
        }
        int rem = *sh_rem;
        int cum = s - tot;
        #pragma unroll
        for (int q = 7; q >= 0; q--) {
            int prev = cum;
            cum += loc[q];
            if (cum >= rem && prev < rem) {
                *sh_rem    = rem - prev;
                *sh_prefix = *sh_prefix | ((unsigned)(b0 + q) << shift);
            }
        }
    }
    __syncthreads();
}
__constant__ unsigned c_mask[4] = {0u, 0xFF000000u, 0xFFFF0000u, 0xFFFFFF00u};

// ---------------- kernel 2: per-(b,cls,chunk) local top-500 ----------------
__global__ void __launch_bounds__(512)
topk_chunk_kernel() {
    __shared__ unsigned skey[CHUNK];
    __shared__ int hist[256];
    __shared__ unsigned sh_prefix;
    __shared__ int sh_rem, cgt, ceq;

    int blk = blockIdx.x;
    int bc  = blk >> 2, chunk = blk & 3;
    int tid = threadIdx.x, nt = blockDim.x;
    const float* src = g_hm + (long)bc * NVOX + chunk * CHUNK;

    for (int v = tid; v < CHUNK; v += nt) skey[v] = key_of(src[v]);
    if (tid == 0) { sh_prefix = 0; sh_rem = TOPK; }
    if (tid < 256) hist[tid] = 0;
    __syncthreads();

    #pragma unroll
    for (int p = 0; p < 4; p++) {
        int shift = 24 - 8*p;
        unsigned mask = c_mask[p], pref = sh_prefix;
        for (int v = tid; v < CHUNK; v += nt) {
            unsigned k = skey[v];
            hist_add(hist, (k >> shift) & 0xFF, (k & mask) == pref);
        }
        pick_bucket(hist, &sh_prefix, &sh_rem, shift);
        if (tid < 256) hist[tid] = 0;
        if (p == 3 && tid == 0) { cgt = 0; ceq = 0; }
        __syncthreads();
    }
    unsigned T = sh_prefix;
    int nEq = sh_rem;
    int nGt = TOPK - nEq;

    float* outS = g_cand_score + blk * TOPK;
    int*   outV = g_cand_vox   + blk * TOPK;
    int voff = chunk * CHUNK;
    for (int v = tid; v < CHUNK; v += nt) {
        unsigned k = skey[v];
        int slot = -1;
        if (k > T)       slot = atomicAdd(&cgt, 1);
        else if (k == T) { int q = atomicAdd(&ceq, 1); if (q < nEq) slot = nGt + q; }
        if (slot >= 0) { outS[slot] = src[v]; outV[slot] = voff + v; }
    }
}

// ---------------- kernel 3: per-batch top-500 of 20000 (rank-by-count) ----------------
__global__ void global_topk_kernel() {
    extern __shared__ unsigned sm3[];
    unsigned* skey = sm3;                                                // [20000]
    unsigned long long* sortb = (unsigned long long*)(sm3 + CAND_PER_B); // [512]
    __shared__ int hist[256];
    __shared__ unsigned sh_prefix;
    __shared__ int sh_rem, cgt, ceq;

    int b = blockIdx.x, tid = threadIdx.x, nt = blockDim.x;
    const float* cs = g_cand_score + (long)b * CAND_PER_B;

    for (int i = tid; i < CAND_PER_B; i += nt) skey[i] = key_of(cs[i]);
    if (tid < 512) sortb[tid] = 0ull;
    if (tid == 0) { sh_prefix = 0; sh_rem = TOPK; }
    if (tid < 256) hist[tid] = 0;
    __syncthreads();

    #pragma unroll
    for (int p = 0; p < 4; p++) {
        int shift = 24 - 8*p;
        unsigned mask = c_mask[p], pref = sh_prefix;
        for (int i = tid; i < CAND_PER_B; i += nt) {
            unsigned k = skey[i];
            hist_add(hist, (k >> shift) & 0xFF, (k & mask) == pref);
        }
        pick_bucket(hist, &sh_prefix, &sh_rem, shift);
        if (tid < 256) hist[tid] = 0;
        if (p == 3 && tid == 0) { cgt = 0; ceq = 0; }
        __syncthreads();
    }
    unsigned T = sh_prefix;
    int nEq = sh_rem;
    int nGt = TOPK - nEq;

    for (int i = tid; i < CAND_PER_B; i += nt) {
        unsigned k = skey[i];
        int slot = -1;
        if (k > T)       slot = atomicAdd(&cgt, 1);
        else if (k == T) { int q = atomicAdd(&ceq, 1); if (q < nEq) slot = nGt + q; }
        if (slot >= 0)
            sortb[slot] = (((unsigned long long)k) << 32) | (unsigned)i;
    }
    __syncthreads();

    if (tid < 512) {
        unsigned long long mine = sortb[tid];
        int rank = 0;
        for (int j = 0; j < 512; j++)
            rank += (sortb[j] > mine);
        if (mine != 0ull && rank < TOPK) {
            int idx = (int)(mine & 0xFFFFFFFFu);
            g_sel_score[b*TOPK + rank] = float_of((unsigned)(mine >> 32));
            g_sel_cls  [b*TOPK + rank] = idx / (NCHUNK*TOPK);
            g_sel_vox  [b*TOPK + rank] = g_cand_vox[(long)b*CAND_PER_B + idx];
        }
    }
}

// ---------------- kernel 4: 5 heads in parallel, latency-optimized ----------------
__global__ void __launch_bounds__(640)
gather_decode_kernel(const float* __restrict__ feats, const int* __restrict__ voxel_xy,
                     const float* __restrict__ W1, const float* __restrict__ b1,
                     const float* __restrict__ gam, const float* __restrict__ bet,
                     const float* __restrict__ mu,  const float* __restrict__ var,
                     const float* __restrict__ W2c, const float* __restrict__ b2c,
                     const float* __restrict__ W2z, const float* __restrict__ b2z,
                     const float* __restrict__ W2d, const float* __restrict__ b2d,
                     const float* __restrict__ W2r, const float* __restrict__ b2r,
                     const float* __restrict__ W2v, const float* __restrict__ b2v,
                     float* __restrict__ out) {
    int e0  = blockIdx.x * GD_BATCH;
    int tid = threadIdx.x;
    int hh  = tid >> 7;            // head group 0..4
    int wt  = tid & 127;
    __shared__ float xr[GD_BATCH][C];
    __shared__ float hs[5][GD_BATCH][C];
    __shared__ float res[GD_BATCH][10];
    __shared__ int   svox[GD_BATCH];
    __shared__ float w2sm[1280];   // c@0(256) z@256(128) d@384(384) r@768(256) v@1024(256)

    if (tid < GD_BATCH) svox[tid] = g_sel_vox[e0 + tid];
    // preload all W2 into smem
    if (tid < 256)                    w2sm[tid]        = __ldg(W2c + tid);
    else if (tid < 384)               w2sm[tid]        = __ldg(W2z + tid - 256);
    if (tid >= 384 && tid < 640 - 0) {
        // nothing; handled below
    }
    for (int i = tid; i < 384; i += 640) w2sm[384 + i]  = __ldg(W2d + i);
    for (int i = tid; i < 256; i += 640) w2sm[768 + i]  = __ldg(W2r + i);
    for (int i = tid; i < 256; i += 640) w2sm[1024 + i] = __ldg(W2v + i);
    __syncthreads();

    for (int i = tid; i < GD_BATCH*C; i += 640) {
        int c = i >> 7, k = i & 127;
        int e = e0 + c;
        int row = (e / TOPK) * NVOX + svox[c];
        xr[c][k] = feats[(long)row*C + k];
    }
    __syncthreads();

    int oc, sb, woff; const float* bp2;
    if      (hh == 0) { bp2 = b2c; oc = 2; sb = 0; woff = 0; }
    else if (hh == 1) { bp2 = b2z; oc = 1; sb = 2; woff = 256; }
    else if (hh == 2) { bp2 = b2d; oc = 3; sb = 3; woff = 384; }
    else if (hh == 3) { bp2 = b2r; oc = 2; sb = 6; woff = 768; }
    else              { bp2 = b2v; oc = 2; sb = 8; woff = 1024; }

    // ---- first layer: channel wt for 8 candidates, deep unroll for MLP ----
    {
        int h = hh + 1;
        int hc = h*C + wt;
        float inv = gam[hc] / sqrtf(var[hc] + 1e-5f);
        float bb  = (b1[hc] - mu[hc]) * inv + bet[hc];
        const float* w = W1 + h*C*C + wt;
        float acc[GD_BATCH];
        #pragma unroll
        for (int c = 0; c < GD_BATCH; c++) acc[c] = 0.f;
        #pragma unroll 16
        for (int kk = 0; kk < C; kk++) {
            float wv = __ldg(w + kk*C);
            #pragma unroll
            for (int c = 0; c < GD_BATCH; c++) acc[c] += xr[c][kk] * wv;
        }
        #pragma unroll
        for (int c = 0; c < GD_BATCH; c++) hs[hh][c][wt] = fmaxf(acc[c]*inv + bb, 0.f);
    }
    __syncthreads();

    // ---- second layer: k-parallel, 16 lanes per candidate ----
    {
        int cand = wt >> 4, ln = wt & 15;
        float pc[3] = {0.f, 0.f, 0.f};
        #pragma unroll
        for (int q = 0; q < 8; q++) {
            int kk = ln + q*16;
            float hv = hs[hh][cand][kk];
            #pragma unroll
            for (int col = 0; col < 3; col++)
                if (col < oc) pc[col] += hv * w2sm[woff + kk*oc + col];
        }
        #pragma unroll
        for (int col = 0; col < 3; col++) {
            float v = pc[col];
            v += __shfl_xor_sync(0xffffffff, v, 1);
            v += __shfl_xor_sync(0xffffffff, v, 2);
            v += __shfl_xor_sync(0xffffffff, v, 4);
            v += __shfl_xor_sync(0xffffffff, v, 8);
            pc[col] = v;
        }
        if (ln == 0) {
            #pragma unroll
            for (int col = 0; col < 3; col++)
                if (col < oc) {
                    float a2 = pc[col] + __ldg(bp2 + col);
                    res[cand][sb + col] = (hh == 2) ? expf(a2) : a2;
                }
        }
    }
    __syncthreads();

    if (tid < GD_BATCH) {
        int e = e0 + tid;
        int b = e / TOPK, k = e % TOPK;
        float score = 1.f / (1.f + expf(-g_sel_score[e]));
        int   cls   = g_sel_cls[e];
        int   vox   = svox[tid];
        int   row   = b * NVOX + vox;
        float vx = (float)voxel_xy[row*2 + 0];
        float vy = (float)voxel_xy[row*2 + 1];
        float xs = (vx + res[tid][0]) * 0.6f - 54.0f;
        float ys = (vy + res[tid][1]) * 0.6f - 54.0f;
        float cz = res[tid][2];
        float ang = atan2f(res[tid][7], res[tid][6]);
        bool m = (xs >= -61.2f) && (xs <= 61.2f) &&
                 (ys >= -61.2f) && (ys <= 61.2f) &&
                 (cz >= -10.f)  && (cz <= 10.f)  && (score > 0.1f);
        float mf = m ? 1.f : 0.f;
        float* ob = out + (long)(b*TOPK + k) * 10;
        ob[0] = xs * mf;  ob[1] = ys * mf;  ob[2] = cz * mf;
        ob[3] = res[tid][3] * mf; ob[4] = res[tid][4] * mf; ob[5] = res[tid][5] * mf;
        ob[6] = ang * mf; ob[7] = res[tid][8] * mf; ob[8] = res[tid][9] * mf;
        ob[9] = score * mf;
        int base = b*TOPK + k;
        out[BATCH*TOPK*10                 + base] = m ? (float)(cls + 1) : 0.f;
        out[BATCH*TOPK*10 + BATCH*TOPK   + base] = (float)(vox + b*NVOX);
        out[BATCH*TOPK*10 + 2*BATCH*TOPK + base] = mf;
    }
}

// ---------------- host launcher ----------------
extern "C" void kernel_launch(void* const* d_in, const int* in_sizes, int n_in,
                              void* d_out, int out_size) {
    const float* feats    = (const float*)d_in[0];
    const int*   voxel_xy = (const int*)d_in[1];
    const float* W1  = (const float*)d_in[2];
    const float* b1  = (const float*)d_in[3];
    const float* gam = (const float*)d_in[4];
    const float* bet = (const float*)d_in[5];
    const float* mu  = (const float*)d_in[6];
    const float* var = (const float*)d_in[7];
    const float* W2_hm = (const float*)d_in[8];
    const float* b2_hm = (const float*)d_in[9];
    const float* W2_c  = (const float*)d_in[10];
    const float* b2_c  = (const float*)d_in[11];
    const float* W2_z  = (const float*)d_in[12];
    const float* b2_z  = (const float*)d_in[13];
    const float* W2_d  = (const float*)d_in[14];
    const float* b2_d  = (const float*)d_in[15];
    const float* W2_r  = (const float*)d_in[16];
    const float* b2_r  = (const float*)d_in[17];
    const float* W2_v  = (const float*)d_in[18];
    const float* b2_v  = (const float*)d_in[19];
    float* out = (float*)d_out;

    const int smem1 = SM_FLOATS * (int)sizeof(float);                 // 214528 B
    const int smem3 = CAND_PER_B * (int)sizeof(unsigned) + 512 * 8;
    cudaFuncSetAttribute(hm_kernel,          cudaFuncAttributeMaxDynamicSharedMemorySize, smem1);
    cudaFuncSetAttribute(global_topk_kernel, cudaFuncAttributeMaxDynamicSharedMemorySize, smem3);

    hm_kernel<<<HM_GRID, 256, smem1>>>(feats, W1, b1, gam, bet, mu, var, W2_hm, b2_hm);
    topk_chunk_kernel<<<BATCH * NCLS * NCHUNK, 512>>>();
    global_topk_kernel<<<BATCH, 1024, smem3>>>();
    gather_decode_kernel<<<BATCH * TOPK / GD_BATCH, 640>>>(feats, voxel_xy,
                                                W1, b1, gam, bet, mu, var,
                                                W2_c, b2_c, W2_z, b2_z, W2_d, b2_d,
                                                W2_r, b2_r, W2_v, b2_v, out);
}

// round 11
// speedup vs baseline: 1.0431x; 1.0339x over previous
#include <cuda_runtime.h>
#include <cstdint>

#define BATCH 4
#define NVOX  32768
#define NROWS (BATCH*NVOX)
#define C     128
#define NCLS  10
#define TOPK  500
#define NCHUNK 4
#define CHUNK  (NVOX/NCHUNK)          // 8192
#define CAND_PER_B (NCLS*NCHUNK*TOPK) // 20000
#define GD_BATCH 8
#define NGRP    (BATCH*TOPK/GD_BATCH) // 250

// hm mma.sync config (256 threads, 8 warps 4x2)
#define HM_GRID 148
#define NTILES  (NROWS/128)           // 1024
#define XPAD 132
#define SM_XS  0                      // [128][132] X tile
#define SM_WP  (128*XPAD)             // 16896: packed W fragments [16][16][32][4]
#define SM_W2  (SM_WP + 32768)        // 49664: [128][10]
#define SM_BF  (SM_W2 + C*NCLS)       // 50944: [128]
#define SM_PO  (SM_BF + 128)          // 51072: [2][128][10] (inv[] during prologue)
#define SM_FLOATS (SM_PO + 2560)      // 53632 -> 214528 bytes

// ---------------- device scratch ----------------
__device__ float g_hm[BATCH*NCLS*NVOX];            // raw logits
__device__ float g_cand_score[BATCH*CAND_PER_B];
__device__ int   g_cand_vox[BATCH*CAND_PER_B];
__device__ float g_sel_score[BATCH*TOPK];
__device__ int   g_sel_cls[BATCH*TOPK];
__device__ int   g_sel_vox[BATCH*TOPK];
__device__ float g_res[BATCH*TOPK*10];             // head outputs per candidate

__device__ __forceinline__ uint32_t f2tf32(float x) {
    uint32_t u;
    asm("cvt.rna.tf32.f32 %0, %1;" : "=r"(u) : "f"(x));
    return u;
}
__device__ __forceinline__ void mma_tf32(float* d, const uint32_t* a, const uint32_t* b) {
    asm volatile("mma.sync.aligned.m16n8k8.row.col.f32.tf32.tf32.f32 "
        "{%0,%1,%2,%3}, {%4,%5,%6,%7}, {%8,%9}, {%0,%1,%2,%3};"
        : "+f"(d[0]), "+f"(d[1]), "+f"(d[2]), "+f"(d[3])
        : "r"(a[0]), "r"(a[1]), "r"(a[2]), "r"(a[3]), "r"(b[0]), "r"(b[1]));
}

// ---------------- kernel 1: dense hm head, TF32 mma.sync 3-term split ----------------
__global__ void __launch_bounds__(256, 1)
hm_kernel(const float* __restrict__ feats,
          const float* __restrict__ W1, const float* __restrict__ b1,
          const float* __restrict__ gam, const float* __restrict__ bet,
          const float* __restrict__ mu,  const float* __restrict__ var,
          const float* __restrict__ W2, const float* __restrict__ b2) {
    extern __shared__ float sm[];
    float*  Xs  = sm + SM_XS;
    float*  Wp  = sm + SM_WP;
    float4* Wp4 = reinterpret_cast<float4*>(Wp);
    float*  W2s = sm + SM_W2;
    float*  bfs = sm + SM_BF;
    float*  po2 = sm + SM_PO;              // [2][128][10]; inv[] during prologue

    int tid  = threadIdx.x;
    int wid  = tid >> 5;
    int lane = tid & 31;
    int wm = wid >> 1, wn = wid & 1;       // warp tile: rows wm*32, cols wn*64

    // ---- prologue: fold BN for head 0, pack fragments ----
    if (tid < C) {
        float inv = gam[tid] / sqrtf(var[tid] + 1e-5f);
        po2[tid] = inv;
        bfs[tid] = (b1[tid] - mu[tid]) * inv + bet[tid];
    }
    for (int i = tid; i < C*NCLS; i += 256) W2s[i] = W2[i];
    __syncthreads();
    for (int i = tid; i < C*C; i += 256) {
        int k = i >> 7, c = i & 127;
        float val = W1[i] * po2[c];
        float hi = __uint_as_float(f2tf32(val));
        float lo = __uint_as_float(f2tf32(val - hi));
        int ks   = k >> 3;
        int kk   = k & 7;
        int klo2 = kk & 3;
        int half = kk >> 2;
        int ln   = ((c & 7) << 2) | klo2;
        int nt   = c >> 3;
        int base = (((ks*16) + nt)*32 + ln)*4;
        Wp[base + half]     = hi;
        Wp[base + 2 + half] = lo;
    }
    float b2r[NCLS];
    #pragma unroll
    for (int j = 0; j < NCLS; j++) b2r[j] = __ldg(b2 + j);
    __syncthreads();

    for (int tile = blockIdx.x; tile < NTILES; tile += HM_GRID) {
        int row0 = tile * 128;

        for (int t = tid; t < 128*32; t += 256) {
            int r  = t >> 5;
            int c4 = (t & 31) << 2;
            float4 f = *reinterpret_cast<const float4*>(feats + (long)(row0 + r)*C + c4);
            *reinterpret_cast<float4*>(Xs + r*XPAD + c4) = f;
        }
        __syncthreads();

        float acc[2][8][4];
        #pragma unroll
        for (int mi = 0; mi < 2; mi++)
            #pragma unroll
            for (int ni = 0; ni < 8; ni++)
                #pragma unroll
                for (int q = 0; q < 4; q++) acc[mi][ni][q] = 0.f;

        int arow = wm*32 + (lane >> 2);
        int klo  = lane & 3;

        #pragma unroll 4
        for (int ks = 0; ks < 16; ks++) {
            int k0 = ks * 8;
            uint32_t ahi[2][4], alo[2][4];
            #pragma unroll
            for (int mi = 0; mi < 2; mi++) {
                int rb = arow + mi*16;
                #pragma unroll
                for (int j = 0; j < 4; j++) {
                    int r = rb + (j & 1)*8;
                    int k = k0 + klo + (j >> 1)*4;
                    float x = Xs[r*XPAD + k];
                    uint32_t h = f2tf32(x);
                    ahi[mi][j] = h;
                    alo[mi][j] = f2tf32(x - __uint_as_float(h));
                }
            }
            #pragma unroll
            for (int ni = 0; ni < 8; ni++) {
                int nt = wn*8 + ni;
                float4 v = Wp4[(ks*16 + nt)*32 + lane];
                uint32_t bh[2] = {__float_as_uint(v.x), __float_as_uint(v.y)};
                uint32_t bl[2] = {__float_as_uint(v.z), __float_as_uint(v.w)};
                #pragma unroll
                for (int mi = 0; mi < 2; mi++) {
                    mma_tf32(acc[mi][ni], ahi[mi], bh);
                    mma_tf32(acc[mi][ni], ahi[mi], bl);
                    mma_tf32(acc[mi][ni], alo[mi], bh);
                }
            }
        }

        // ---- epilogue directly from accumulators ----
        float po[4][NCLS];
        #pragma unroll
        for (int s = 0; s < 4; s++)
            #pragma unroll
            for (int j = 0; j < NCLS; j++) po[s][j] = 0.f;

        #pragma unroll
        for (int ni = 0; ni < 8; ni++) {
            #pragma unroll
            for (int t = 0; t < 2; t++) {
                int c = wn*64 + ni*8 + 2*(lane & 3) + t;
                float bfc = bfs[c];
                float w2l[NCLS];
                #pragma unroll
                for (int j = 0; j < NCLS; j++) w2l[j] = W2s[c*NCLS + j];
                #pragma unroll
                for (int mi = 0; mi < 2; mi++) {
                    float h0 = fmaxf(acc[mi][ni][t]     + bfc, 0.f);
                    float h1 = fmaxf(acc[mi][ni][t + 2] + bfc, 0.f);
                    #pragma unroll
                    for (int j = 0; j < NCLS; j++) {
                        po[mi*2 + 0][j] += h0 * w2l[j];
                        po[mi*2 + 1][j] += h1 * w2l[j];
                    }
                }
            }
        }
        #pragma unroll
        for (int s = 0; s < 4; s++)
            #pragma unroll
            for (int j = 0; j < NCLS; j++) {
                float v = po[s][j];
                v += __shfl_xor_sync(0xffffffff, v, 1);
                v += __shfl_xor_sync(0xffffffff, v, 2);
                po[s][j] = v;
            }
        if ((lane & 3) == 0) {
            int rbase = wm*32 + (lane >> 2);
            #pragma unroll
            for (int s = 0; s < 4; s++) {
                int row = rbase + ((s & 1) ? 8 : 0) + ((s >> 1) ? 16 : 0);
                #pragma unroll
                for (int j = 0; j < NCLS; j++)
                    po2[(wn*128 + row)*NCLS + j] = po[s][j];
            }
        }
        __syncthreads();

        {
            int row = tid >> 1;
            int j0  = (tid & 1) * 5;
            int rrow = row0 + row;
            int b    = rrow >> 15;
            int v    = rrow & (NVOX - 1);
            #pragma unroll
            for (int j = 0; j < 5; j++) {
                float val = po2[row*NCLS + j0 + j] + po2[(128 + row)*NCLS + j0 + j] + b2r[j0 + j];
                g_hm[((long)(b*NCLS + j0 + j))*NVOX + v] = val;
            }
        }
        __syncthreads();
    }
}

// ---------------- radix helpers ----------------
__device__ __forceinline__ unsigned key_of(float f) {
    unsigned u = __float_as_uint(f);
    return (u & 0x80000000u) ? ~u : (u | 0x80000000u);
}
__device__ __forceinline__ float float_of(unsigned k) {
    unsigned u = (k & 0x80000000u) ? (k & 0x7FFFFFFFu) : ~k;
    return __uint_as_float(u);
}
__device__ __forceinline__ void hist_add(int* hist, unsigned bin, bool act) {
    unsigned lm = __activemask();
    unsigned amask = __ballot_sync(lm, act);
    if (act) {
        unsigned peers = __match_any_sync(amask, bin);
        int leader = __ffs(peers) - 1;
        if ((int)(threadIdx.x & 31) == leader)
            atomicAdd(&hist[bin], __popc(peers));
    }
}
__device__ __forceinline__ void pick_bucket(int* hist, unsigned* sh_prefix,
                                            int* sh_rem, int shift) {
    __syncthreads();
    if (threadIdx.x < 32) {
        int lane = threadIdx.x;
        int b0 = lane * 8;
        int loc[8];
        int tot = 0;
        #pragma unroll
        for (int q = 0; q < 8; q++) { loc[q] = hist[b0 + q]; tot += loc[q]; }
        int s = tot;
        #pragma unroll
        for (int off = 1; off < 32; off <<= 1) {
            int t = __shfl_down_sync(0xffffffff, s, off);
            if (lane + off < 32) s += t;
        }
        int rem = *sh_rem;
        int cum = s - tot;
        #pragma unroll
        for (int q = 7; q >= 0; q--) {
            int prev = cum;
            cum += loc[q];
            if (cum >= rem && prev < rem) {
                *sh_rem    = rem - prev;
                *sh_prefix = *sh_prefix | ((unsigned)(b0 + q) << shift);
            }
        }
    }
    __syncthreads();
}
__constant__ unsigned c_mask[4] = {0u, 0xFF000000u, 0xFFFF0000u, 0xFFFFFF00u};

// ---------------- kernel 2: per-(b,cls,chunk) local top-500 ----------------
__global__ void __launch_bounds__(512)
topk_chunk_kernel() {
    __shared__ unsigned skey[CHUNK];
    __shared__ int hist[256];
    __shared__ unsigned sh_prefix;
    __shared__ int sh_rem, cgt, ceq;

    int blk = blockIdx.x;
    int bc  = blk >> 2, chunk = blk & 3;
    int tid = threadIdx.x, nt = blockDim.x;
    const float* src = g_hm + (long)bc * NVOX + chunk * CHUNK;

    for (int v = tid; v < CHUNK; v += nt) skey[v] = key_of(src[v]);
    if (tid == 0) { sh_prefix = 0; sh_rem = TOPK; }
    if (tid < 256) hist[tid] = 0;
    __syncthreads();

    #pragma unroll
    for (int p = 0; p < 4; p++) {
        int shift = 24 - 8*p;
        unsigned mask = c_mask[p], pref = sh_prefix;
        for (int v = tid; v < CHUNK; v += nt) {
            unsigned k = skey[v];
            hist_add(hist, (k >> shift) & 0xFF, (k & mask) == pref);
        }
        pick_bucket(hist, &sh_prefix, &sh_rem, shift);
        if (tid < 256) hist[tid] = 0;
        if (p == 3 && tid == 0) { cgt = 0; ceq = 0; }
        __syncthreads();
    }
    unsigned T = sh_prefix;
    int nEq = sh_rem;
    int nGt = TOPK - nEq;

    float* outS = g_cand_score + blk * TOPK;
    int*   outV = g_cand_vox   + blk * TOPK;
    int voff = chunk * CHUNK;
    for (int v = tid; v < CHUNK; v += nt) {
        unsigned k = skey[v];
        int slot = -1;
        if (k > T)       slot = atomicAdd(&cgt, 1);
        else if (k == T) { int q = atomicAdd(&ceq, 1); if (q < nEq) slot = nGt + q; }
        if (slot >= 0) { outS[slot] = src[v]; outV[slot] = voff + v; }
    }
}

// ---------------- kernel 3: per-batch top-500 of 20000 (rank-by-count) ----------------
__global__ void global_topk_kernel() {
    extern __shared__ unsigned sm3[];
    unsigned* skey = sm3;                                                // [20000]
    unsigned long long* sortb = (unsigned long long*)(sm3 + CAND_PER_B); // [512]
    __shared__ int hist[256];
    __shared__ unsigned sh_prefix;
    __shared__ int sh_rem, cgt, ceq;

    int b = blockIdx.x, tid = threadIdx.x, nt = blockDim.x;
    const float* cs = g_cand_score + (long)b * CAND_PER_B;

    for (int i = tid; i < CAND_PER_B; i += nt) skey[i] = key_of(cs[i]);
    if (tid < 512) sortb[tid] = 0ull;
    if (tid == 0) { sh_prefix = 0; sh_rem = TOPK; }
    if (tid < 256) hist[tid] = 0;
    __syncthreads();

    #pragma unroll
    for (int p = 0; p < 4; p++) {
        int shift = 24 - 8*p;
        unsigned mask = c_mask[p], pref = sh_prefix;
        for (int i = tid; i < CAND_PER_B; i += nt) {
            unsigned k = skey[i];
            hist_add(hist, (k >> shift) & 0xFF, (k & mask) == pref);
        }
        pick_bucket(hist, &sh_prefix, &sh_rem, shift);
        if (tid < 256) hist[tid] = 0;
        if (p == 3 && tid == 0) { cgt = 0; ceq = 0; }
        __syncthreads();
    }
    unsigned T = sh_prefix;
    int nEq = sh_rem;
    int nGt = TOPK - nEq;

    for (int i = tid; i < CAND_PER_B; i += nt) {
        unsigned k = skey[i];
        int slot = -1;
        if (k > T)       slot = atomicAdd(&cgt, 1);
        else if (k == T) { int q = atomicAdd(&ceq, 1); if (q < nEq) slot = nGt + q; }
        if (slot >= 0)
            sortb[slot] = (((unsigned long long)k) << 32) | (unsigned)i;
    }
    __syncthreads();

    if (tid < 512) {
        unsigned long long mine = sortb[tid];
        int rank = 0;
        for (int j = 0; j < 512; j++)
            rank += (sortb[j] > mine);
        if (mine != 0ull && rank < TOPK) {
            int idx = (int)(mine & 0xFFFFFFFFu);
            g_sel_score[b*TOPK + rank] = float_of((unsigned)(mine >> 32));
            g_sel_cls  [b*TOPK + rank] = idx / (NCHUNK*TOPK);
            g_sel_vox  [b*TOPK + rank] = g_cand_vox[(long)b*CAND_PER_B + idx];
        }
    }
}

// ---------------- kernel 4a: one (cand-group, head) per 128-thread block ----------------
__global__ void __launch_bounds__(128)
head_kernel(const float* __restrict__ feats,
            const float* __restrict__ W1, const float* __restrict__ b1,
            const float* __restrict__ gam, const float* __restrict__ bet,
            const float* __restrict__ mu,  const float* __restrict__ var,
            const float* __restrict__ W2c, const float* __restrict__ b2c,
            const float* __restrict__ W2z, const float* __restrict__ b2z,
            const float* __restrict__ W2d, const float* __restrict__ b2d,
            const float* __restrict__ W2r, const float* __restrict__ b2r,
            const float* __restrict__ W2v, const float* __restrict__ b2v) {
    int hh  = blockIdx.x / NGRP;       // 0..4 (same-head blocks adjacent -> L2-hot W1)
    int grp = blockIdx.x % NGRP;
    int e0  = grp * GD_BATCH;
    int wt  = threadIdx.x;
    __shared__ float xr[GD_BATCH][C];
    __shared__ float hs[GD_BATCH][C];
    __shared__ int   svox[GD_BATCH];

    if (wt < GD_BATCH) svox[wt] = g_sel_vox[e0 + wt];
    __syncthreads();

    #pragma unroll
    for (int c = 0; c < GD_BATCH; c++) {
        int e = e0 + c;
        int row = (e / TOPK) * NVOX + svox[c];
        xr[c][wt] = __ldg(feats + (long)row*C + wt);
    }
    __syncthreads();

    const float* w2; const float* bp2; int oc, sb;
    if      (hh == 0) { w2 = W2c; bp2 = b2c; oc = 2; sb = 0; }
    else if (hh == 1) { w2 = W2z; bp2 = b2z; oc = 1; sb = 2; }
    else if (hh == 2) { w2 = W2d; bp2 = b2d; oc = 3; sb = 3; }
    else if (hh == 3) { w2 = W2r; bp2 = b2r; oc = 2; sb = 6; }
    else              { w2 = W2v; bp2 = b2v; oc = 2; sb = 8; }

    // first layer: channel wt for all 8 candidates (BN folded on the fly)
    {
        int h = hh + 1;
        int hc = h*C + wt;
        float inv = gam[hc] / sqrtf(var[hc] + 1e-5f);
        float bb  = (b1[hc] - mu[hc]) * inv + bet[hc];
        const float* w = W1 + h*C*C + wt;
        float acc[GD_BATCH];
        #pragma unroll
        for (int c = 0; c < GD_BATCH; c++) acc[c] = 0.f;
        #pragma unroll 16
        for (int kk = 0; kk < C; kk++) {
            float wv = __ldg(w + kk*C);
            #pragma unroll
            for (int c = 0; c < GD_BATCH; c++) acc[c] += xr[c][kk] * wv;
        }
        #pragma unroll
        for (int c = 0; c < GD_BATCH; c++) hs[c][wt] = fmaxf(acc[c]*inv + bb, 0.f);
    }
    __syncthreads();

    // second layer: k-parallel, 16 lanes per candidate
    {
        int cand = wt >> 4, ln = wt & 15;
        float pc[3] = {0.f, 0.f, 0.f};
        #pragma unroll
        for (int q = 0; q < 8; q++) {
            int kk = ln + q*16;
            float hv = hs[cand][kk];
            #pragma unroll
            for (int col = 0; col < 3; col++)
                if (col < oc) pc[col] += hv * __ldg(w2 + kk*oc + col);
        }
        #pragma unroll
        for (int col = 0; col < 3; col++) {
            float v = pc[col];
            v += __shfl_xor_sync(0xffffffff, v, 1);
            v += __shfl_xor_sync(0xffffffff, v, 2);
            v += __shfl_xor_sync(0xffffffff, v, 4);
            v += __shfl_xor_sync(0xffffffff, v, 8);
            pc[col] = v;
        }
        if (ln == 0) {
            int e = e0 + cand;
            #pragma unroll
            for (int col = 0; col < 3; col++)
                if (col < oc) {
                    float a2 = pc[col] + __ldg(bp2 + col);
                    g_res[e*10 + sb + col] = (hh == 2) ? expf(a2) : a2;
                }
        }
    }
}

// ---------------- kernel 4b: per-candidate decode ----------------
__global__ void __launch_bounds__(256)
decode_kernel(const int* __restrict__ voxel_xy, float* __restrict__ out) {
    int e = blockIdx.x * 256 + threadIdx.x;
    if (e >= BATCH*TOPK) return;
    int b = e / TOPK, k = e % TOPK;
    float score = 1.f / (1.f + expf(-g_sel_score[e]));
    int   cls   = g_sel_cls[e];
    int   vox   = g_sel_vox[e];
    int   row   = b * NVOX + vox;
    const float* r = g_res + e*10;
    float vx = (float)voxel_xy[row*2 + 0];
    float vy = (float)voxel_xy[row*2 + 1];
    float xs = (vx + r[0]) * 0.6f - 54.0f;
    float ys = (vy + r[1]) * 0.6f - 54.0f;
    float cz = r[2];
    float ang = atan2f(r[7], r[6]);
    bool m = (xs >= -61.2f) && (xs <= 61.2f) &&
             (ys >= -61.2f) && (ys <= 61.2f) &&
             (cz >= -10.f)  && (cz <= 10.f)  && (score > 0.1f);
    float mf = m ? 1.f : 0.f;
    float* ob = out + (long)(b*TOPK + k) * 10;
    ob[0] = xs * mf;  ob[1] = ys * mf;  ob[2] = cz * mf;
    ob[3] = r[3] * mf; ob[4] = r[4] * mf; ob[5] = r[5] * mf;
    ob[6] = ang * mf; ob[7] = r[8] * mf; ob[8] = r[9] * mf;
    ob[9] = score * mf;
    int base = b*TOPK + k;
    out[BATCH*TOPK*10                 + base] = m ? (float)(cls + 1) : 0.f;
    out[BATCH*TOPK*10 + BATCH*TOPK   + base] = (float)(vox + b*NVOX);
    out[BATCH*TOPK*10 + 2*BATCH*TOPK + base] = mf;
}

// ---------------- host launcher ----------------
extern "C" void kernel_launch(void* const* d_in, const int* in_sizes, int n_in,
                              void* d_out, int out_size) {
    const float* feats    = (const float*)d_in[0];
    const int*   voxel_xy = (const int*)d_in[1];
    const float* W1  = (const float*)d_in[2];
    const float* b1  = (const float*)d_in[3];
    const float* gam = (const float*)d_in[4];
    const float* bet = (const float*)d_in[5];
    const float* mu  = (const float*)d_in[6];
    const float* var = (const float*)d_in[7];
    const float* W2_hm = (const float*)d_in[8];
    const float* b2_hm = (const float*)d_in[9];
    const float* W2_c  = (const float*)d_in[10];
    const float* b2_c  = (const float*)d_in[11];
    const float* W2_z  = (const float*)d_in[12];
    const float* b2_z  = (const float*)d_in[13];
    const float* W2_d  = (const float*)d_in[14];
    const float* b2_d  = (const float*)d_in[15];
    const float* W2_r  = (const float*)d_in[16];
    const float* b2_r  = (const float*)d_in[17];
    const float* W2_v  = (const float*)d_in[18];
    const float* b2_v  = (const float*)d_in[19];
    float* out = (float*)d_out;

    const int smem1 = SM_FLOATS * (int)sizeof(float);                 // 214528 B
    const int smem3 = CAND_PER_B * (int)sizeof(unsigned) + 512 * 8;
    cudaFuncSetAttribute(hm_kernel,          cudaFuncAttributeMaxDynamicSharedMemorySize, smem1);
    cudaFuncSetAttribute(global_topk_kernel, cudaFuncAttributeMaxDynamicSharedMemorySize, smem3);

    hm_kernel<<<HM_GRID, 256, smem1>>>(feats, W1, b1, gam, bet, mu, var, W2_hm, b2_hm);
    topk_chunk_kernel<<<BATCH * NCLS * NCHUNK, 512>>>();
    global_topk_kernel<<<BATCH, 1024, smem3>>>();
    head_kernel<<<5 * NGRP, 128>>>(feats, W1, b1, gam, bet, mu, var,
                                   W2_c, b2_c, W2_z, b2_z, W2_d, b2_d,
                                   W2_r, b2_r, W2_v, b2_v);
    decode_kernel<<<(BATCH*TOPK + 255)/256, 256>>>(voxel_xy, out);
}

// round 12
// speedup vs baseline: 1.0568x; 1.0131x over previous
#include <cuda_runtime.h>
#include <cstdint>

#define BATCH 4
#define NVOX  32768
#define NROWS (BATCH*NVOX)
#define C     128
#define NCLS  10
#define TOPK  500
#define NCHUNK 4
#define CHUNK  (NVOX/NCHUNK)          // 8192
#define CAND_PER_B (NCLS*NCHUNK*TOPK) // 20000
#define GD_BATCH 8
#define NGRP    (BATCH*TOPK/GD_BATCH) // 250

// hm mma.sync config (256 threads, 8 warps 4x2)
#define HM_GRID 148
#define NTILES  (NROWS/128)           // 1024
#define XPAD 132
#define SM_XS  0                      // [128][132] X tile
#define SM_WP  (128*XPAD)             // 16896: packed W fragments [16][16][32][4]
#define SM_W2  (SM_WP + 32768)        // 49664: [128][10]
#define SM_BF  (SM_W2 + C*NCLS)       // 50944: [128]
#define SM_PO  (SM_BF + 128)          // 51072: [2][128][10] (inv[] during prologue)
#define SM_FLOATS (SM_PO + 2560)      // 53632 -> 214528 bytes

// ---------------- device scratch ----------------
__device__ float g_hm[BATCH*NCLS*NVOX];            // raw logits
__device__ float g_cand_score[BATCH*CAND_PER_B];
__device__ int   g_cand_vox[BATCH*CAND_PER_B];
__device__ float g_sel_score[BATCH*TOPK];
__device__ int   g_sel_cls[BATCH*TOPK];
__device__ int   g_sel_vox[BATCH*TOPK];
__device__ float g_res[BATCH*TOPK*10];             // head outputs per candidate

__device__ __forceinline__ uint32_t f2tf32(float x) {
    uint32_t u;
    asm("cvt.rna.tf32.f32 %0, %1;" : "=r"(u) : "f"(x));
    return u;
}
__device__ __forceinline__ void mma_tf32(float* d, const uint32_t* a, const uint32_t* b) {
    asm volatile("mma.sync.aligned.m16n8k8.row.col.f32.tf32.tf32.f32 "
        "{%0,%1,%2,%3}, {%4,%5,%6,%7}, {%8,%9}, {%0,%1,%2,%3};"
        : "+f"(d[0]), "+f"(d[1]), "+f"(d[2]), "+f"(d[3])
        : "r"(a[0]), "r"(a[1]), "r"(a[2]), "r"(a[3]), "r"(b[0]), "r"(b[1]));
}
__device__ __forceinline__ void cp_async16(uint32_t smem_addr, const void* gptr) {
    asm volatile("cp.async.cg.shared.global [%0], [%1], 16;" :: "r"(smem_addr), "l"(gptr));
}
#define CP_COMMIT() asm volatile("cp.async.commit_group;" ::: "memory")
#define CP_WAIT0()  asm volatile("cp.async.wait_group 0;" ::: "memory")

// ---------------- kernel 1: dense hm head, TF32 mma.sync 3-term split ----------------
__global__ void __launch_bounds__(256, 1)
hm_kernel(const float* __restrict__ feats,
          const float* __restrict__ W1, const float* __restrict__ b1,
          const float* __restrict__ gam, const float* __restrict__ bet,
          const float* __restrict__ mu,  const float* __restrict__ var,
          const float* __restrict__ W2, const float* __restrict__ b2) {
    extern __shared__ float sm[];
    float*  Xs  = sm + SM_XS;
    float*  Wp  = sm + SM_WP;
    float4* Wp4 = reinterpret_cast<float4*>(Wp);
    float*  W2s = sm + SM_W2;
    float*  bfs = sm + SM_BF;
    float*  po2 = sm + SM_PO;              // [2][128][10]; inv[] during prologue

    int tid  = threadIdx.x;
    int wid  = tid >> 5;
    int lane = tid & 31;
    int wm = wid >> 1, wn = wid & 1;       // warp tile: rows wm*32, cols wn*64

    uint32_t xs_base = (uint32_t)__cvta_generic_to_shared(Xs);
    int lr  = tid >> 5;                    // load row stride pattern
    int lc4 = (tid & 31) << 2;

    // issue async load of the FIRST tile (overlaps prologue)
    int tile0 = blockIdx.x;
    {
        int row0 = tile0 * 128;
        for (int r = lr; r < 128; r += 8)
            cp_async16(xs_base + (uint32_t)(r*XPAD + lc4)*4u,
                       feats + (long)(row0 + r)*C + lc4);
        CP_COMMIT();
    }

    // ---- prologue: fold BN for head 0, pack fragments ----
    if (tid < C) {
        float inv = gam[tid] / sqrtf(var[tid] + 1e-5f);
        po2[tid] = inv;
        bfs[tid] = (b1[tid] - mu[tid]) * inv + bet[tid];
    }
    for (int i = tid; i < C*NCLS; i += 256) W2s[i] = W2[i];
    __syncthreads();
    for (int i = tid; i < C*C; i += 256) {
        int k = i >> 7, c = i & 127;
        float val = W1[i] * po2[c];
        float hi = __uint_as_float(f2tf32(val));
        float lo = __uint_as_float(f2tf32(val - hi));
        int ks   = k >> 3;
        int kk   = k & 7;
        int klo2 = kk & 3;
        int half = kk >> 2;
        int ln   = ((c & 7) << 2) | klo2;
        int nt   = c >> 3;
        int base = (((ks*16) + nt)*32 + ln)*4;
        Wp[base + half]     = hi;
        Wp[base + 2 + half] = lo;
    }
    float b2r[NCLS];
    #pragma unroll
    for (int j = 0; j < NCLS; j++) b2r[j] = __ldg(b2 + j);

    for (int tile = tile0; tile < NTILES; tile += HM_GRID) {
        int row0 = tile * 128;
        CP_WAIT0();
        __syncthreads();        // Xs ready (and po2/inv free after first pass)

        float acc[2][8][4];
        #pragma unroll
        for (int mi = 0; mi < 2; mi++)
            #pragma unroll
            for (int ni = 0; ni < 8; ni++)
                #pragma unroll
                for (int q = 0; q < 4; q++) acc[mi][ni][q] = 0.f;

        int arow = wm*32 + (lane >> 2);
        int klo  = lane & 3;

        #pragma unroll 4
        for (int ks = 0; ks < 16; ks++) {
            int k0 = ks * 8;
            uint32_t ahi[2][4], alo[2][4];
            #pragma unroll
            for (int mi = 0; mi < 2; mi++) {
                int rb = arow + mi*16;
                #pragma unroll
                for (int j = 0; j < 4; j++) {
                    int r = rb + (j & 1)*8;
                    int k = k0 + klo + (j >> 1)*4;
                    float x = Xs[r*XPAD + k];
                    uint32_t h = f2tf32(x);
                    ahi[mi][j] = h;
                    alo[mi][j] = f2tf32(x - __uint_as_float(h));
                }
            }
            #pragma unroll
            for (int ni = 0; ni < 8; ni++) {
                int nt = wn*8 + ni;
                float4 v = Wp4[(ks*16 + nt)*32 + lane];
                uint32_t bh[2] = {__float_as_uint(v.x), __float_as_uint(v.y)};
                uint32_t bl[2] = {__float_as_uint(v.z), __float_as_uint(v.w)};
                #pragma unroll
                for (int mi = 0; mi < 2; mi++) {
                    mma_tf32(acc[mi][ni], ahi[mi], bh);
                    mma_tf32(acc[mi][ni], ahi[mi], bl);
                    mma_tf32(acc[mi][ni], alo[mi], bh);
                }
            }
        }
        __syncthreads();        // all warps done READING Xs

        // prefetch next tile while epilogue computes
        int ntile = tile + HM_GRID;
        if (ntile < NTILES) {
            int nrow0 = ntile * 128;
            for (int r = lr; r < 128; r += 8)
                cp_async16(xs_base + (uint32_t)(r*XPAD + lc4)*4u,
                           feats + (long)(nrow0 + r)*C + lc4);
        }
        CP_COMMIT();

        // ---- epilogue directly from accumulators ----
        float po[4][NCLS];
        #pragma unroll
        for (int s = 0; s < 4; s++)
            #pragma unroll
            for (int j = 0; j < NCLS; j++) po[s][j] = 0.f;

        #pragma unroll
        for (int ni = 0; ni < 8; ni++) {
            #pragma unroll
            for (int t = 0; t < 2; t++) {
                int c = wn*64 + ni*8 + 2*(lane & 3) + t;
                float bfc = bfs[c];
                float w2l[NCLS];
                #pragma unroll
                for (int j = 0; j < NCLS; j++) w2l[j] = W2s[c*NCLS + j];
                #pragma unroll
                for (int mi = 0; mi < 2; mi++) {
                    float h0 = fmaxf(acc[mi][ni][t]     + bfc, 0.f);
                    float h1 = fmaxf(acc[mi][ni][t + 2] + bfc, 0.f);
                    #pragma unroll
                    for (int j = 0; j < NCLS; j++) {
                        po[mi*2 + 0][j] += h0 * w2l[j];
                        po[mi*2 + 1][j] += h1 * w2l[j];
                    }
                }
            }
        }
        #pragma unroll
        for (int s = 0; s < 4; s++)
            #pragma unroll
            for (int j = 0; j < NCLS; j++) {
                float v = po[s][j];
                v += __shfl_xor_sync(0xffffffff, v, 1);
                v += __shfl_xor_sync(0xffffffff, v, 2);
                po[s][j] = v;
            }
        if ((lane & 3) == 0) {
            int rbase = wm*32 + (lane >> 2);
            #pragma unroll
            for (int s = 0; s < 4; s++) {
                int row = rbase + ((s & 1) ? 8 : 0) + ((s >> 1) ? 16 : 0);
                #pragma unroll
                for (int j = 0; j < NCLS; j++)
                    po2[(wn*128 + row)*NCLS + j] = po[s][j];
            }
        }
        __syncthreads();

        {
            int row = tid >> 1;
            int j0  = (tid & 1) * 5;
            int rrow = row0 + row;
            int b    = rrow >> 15;
            int v    = rrow & (NVOX - 1);
            #pragma unroll
            for (int j = 0; j < 5; j++) {
                float val = po2[row*NCLS + j0 + j] + po2[(128 + row)*NCLS + j0 + j] + b2r[j0 + j];
                g_hm[((long)(b*NCLS + j0 + j))*NVOX + v] = val;
            }
        }
        // loop-top CP_WAIT0 + syncthreads orders po2 reuse & Xs overwrite
    }
}

// ---------------- radix helpers ----------------
__device__ __forceinline__ unsigned key_of(float f) {
    unsigned u = __float_as_uint(f);
    return (u & 0x80000000u) ? ~u : (u | 0x80000000u);
}
__device__ __forceinline__ float float_of(unsigned k) {
    unsigned u = (k & 0x80000000u) ? (k & 0x7FFFFFFFu) : ~k;
    return __uint_as_float(u);
}
__device__ __forceinline__ void hist_add(int* hist, unsigned bin, bool act) {
    unsigned lm = __activemask();
    unsigned amask = __ballot_sync(lm, act);
    if (act) {
        unsigned peers = __match_any_sync(amask, bin);
        int leader = __ffs(peers) - 1;
        if ((int)(threadIdx.x & 31) == leader)
            atomicAdd(&hist[bin], __popc(peers));
    }
}
__device__ __forceinline__ void pick_bucket(int* hist, unsigned* sh_prefix,
                                            int* sh_rem, int shift) {
    __syncthreads();
    if (threadIdx.x < 32) {
        int lane = threadIdx.x;
        int b0 = lane * 8;
        int loc[8];
        int tot = 0;
        #pragma unroll
        for (int q = 0; q < 8; q++) { loc[q] = hist[b0 + q]; tot += loc[q]; }
        int s = tot;
        #pragma unroll
        for (int off = 1; off < 32; off <<= 1) {
            int t = __shfl_down_sync(0xffffffff, s, off);
            if (lane + off < 32) s += t;
        }
        int rem = *sh_rem;
        int cum = s - tot;
        #pragma unroll
        for (int q = 7; q >= 0; q--) {
            int prev = cum;
            cum += loc[q];
            if (cum >= rem && prev < rem) {
                *sh_rem    = rem - prev;
                *sh_prefix = *sh_prefix | ((unsigned)(b0 + q) << shift);
            }
        }
    }
    __syncthreads();
}
__constant__ unsigned c_mask[4] = {0u, 0xFF000000u, 0xFFFF0000u, 0xFFFFFF00u};

// ---------------- kernel 2: per-(b,cls,chunk) local top-500 ----------------
__global__ void __launch_bounds__(512)
topk_chunk_kernel() {
    __shared__ unsigned skey[CHUNK];
    __shared__ int hist[256];
    __shared__ unsigned sh_prefix;
    __shared__ int sh_rem, cgt, ceq;

    int blk = blockIdx.x;
    int bc  = blk >> 2, chunk = blk & 3;
    int tid = threadIdx.x, nt = blockDim.x;
    const float* src = g_hm + (long)bc * NVOX + chunk * CHUNK;

    for (int v = tid; v < CHUNK; v += nt) skey[v] = key_of(src[v]);
    if (tid == 0) { sh_prefix = 0; sh_rem = TOPK; }
    if (tid < 256) hist[tid] = 0;
    __syncthreads();

    #pragma unroll
    for (int p = 0; p < 4; p++) {
        int shift = 24 - 8*p;
        unsigned mask = c_mask[p], pref = sh_prefix;
        for (int v = tid; v < CHUNK; v += nt) {
            unsigned k = skey[v];
            hist_add(hist, (k >> shift) & 0xFF, (k & mask) == pref);
        }
        pick_bucket(hist, &sh_prefix, &sh_rem, shift);
        if (tid < 256) hist[tid] = 0;
        if (p == 3 && tid == 0) { cgt = 0; ceq = 0; }
        __syncthreads();
    }
    unsigned T = sh_prefix;
    int nEq = sh_rem;
    int nGt = TOPK - nEq;

    float* outS = g_cand_score + blk * TOPK;
    int*   outV = g_cand_vox   + blk * TOPK;
    int voff = chunk * CHUNK;
    for (int v = tid; v < CHUNK; v += nt) {
        unsigned k = skey[v];
        int slot = -1;
        if (k > T)       slot = atomicAdd(&cgt, 1);
        else if (k == T) { int q = atomicAdd(&ceq, 1); if (q < nEq) slot = nGt + q; }
        if (slot >= 0) { outS[slot] = src[v]; outV[slot] = voff + v; }
    }
}

// ---------------- kernel 3: per-batch top-500 of 20000 (rank-by-count) ----------------
__global__ void global_topk_kernel() {
    extern __shared__ unsigned sm3[];
    unsigned* skey = sm3;                                                // [20000]
    unsigned long long* sortb = (unsigned long long*)(sm3 + CAND_PER_B); // [512]
    __shared__ int hist[256];
    __shared__ unsigned sh_prefix;
    __shared__ int sh_rem, cgt, ceq;

    int b = blockIdx.x, tid = threadIdx.x, nt = blockDim.x;
    const float* cs = g_cand_score + (long)b * CAND_PER_B;

    for (int i = tid; i < CAND_PER_B; i += nt) skey[i] = key_of(cs[i]);
    if (tid < 512) sortb[tid] = 0ull;
    if (tid == 0) { sh_prefix = 0; sh_rem = TOPK; }
    if (tid < 256) hist[tid] = 0;
    __syncthreads();

    #pragma unroll
    for (int p = 0; p < 4; p++) {
        int shift = 24 - 8*p;
        unsigned mask = c_mask[p], pref = sh_prefix;
        for (int i = tid; i < CAND_PER_B; i += nt) {
            unsigned k = skey[i];
            hist_add(hist, (k >> shift) & 0xFF, (k & mask) == pref);
        }
        pick_bucket(hist, &sh_prefix, &sh_rem, shift);
        if (tid < 256) hist[tid] = 0;
        if (p == 3 && tid == 0) { cgt = 0; ceq = 0; }
        __syncthreads();
    }
    unsigned T = sh_prefix;
    int nEq = sh_rem;
    int nGt = TOPK - nEq;

    for (int i = tid; i < CAND_PER_B; i += nt) {
        unsigned k = skey[i];
        int slot = -1;
        if (k > T)       slot = atomicAdd(&cgt, 1);
        else if (k == T) { int q = atomicAdd(&ceq, 1); if (q < nEq) slot = nGt + q; }
        if (slot >= 0)
            sortb[slot] = (((unsigned long long)k) << 32) | (unsigned)i;
    }
    __syncthreads();

    if (tid < 512) {
        unsigned long long mine = sortb[tid];
        int rank = 0;
        for (int j = 0; j < 512; j++)
            rank += (sortb[j] > mine);
        if (mine != 0ull && rank < TOPK) {
            int idx = (int)(mine & 0xFFFFFFFFu);
            g_sel_score[b*TOPK + rank] = float_of((unsigned)(mine >> 32));
            g_sel_cls  [b*TOPK + rank] = idx / (NCHUNK*TOPK);
            g_sel_vox  [b*TOPK + rank] = g_cand_vox[(long)b*CAND_PER_B + idx];
        }
    }
}

// ---------------- kernel 4a: one (cand-group, head) per 128-thread block ----------------
__global__ void __launch_bounds__(128)
head_kernel(const float* __restrict__ feats,
            const float* __restrict__ W1, const float* __restrict__ b1,
            const float* __restrict__ gam, const float* __restrict__ bet,
            const float* __restrict__ mu,  const float* __restrict__ var,
            const float* __restrict__ W2c, const float* __restrict__ b2c,
            const float* __restrict__ W2z, const float* __restrict__ b2z,
            const float* __restrict__ W2d, const float* __restrict__ b2d,
            const float* __restrict__ W2r, const float* __restrict__ b2r,
            const float* __restrict__ W2v, const float* __restrict__ b2v) {
    int hh  = blockIdx.x / NGRP;       // 0..4 (same-head blocks adjacent -> L2-hot W1)
    int grp = blockIdx.x % NGRP;
    int e0  = grp * GD_BATCH;
    int wt  = threadIdx.x;
    __shared__ __align__(16) float xr[GD_BATCH][C];
    __shared__ __align__(16) float hs[GD_BATCH][C];
    __shared__ int svox[GD_BATCH];

    if (wt < GD_BATCH) svox[wt] = g_sel_vox[e0 + wt];
    __syncthreads();

    #pragma unroll
    for (int c = 0; c < GD_BATCH; c++) {
        int e = e0 + c;
        int row = (e / TOPK) * NVOX + svox[c];
        xr[c][wt] = __ldg(feats + (long)row*C + wt);
    }
    __syncthreads();

    const float* w2; const float* bp2; int oc, sb;
    if      (hh == 0) { w2 = W2c; bp2 = b2c; oc = 2; sb = 0; }
    else if (hh == 1) { w2 = W2z; bp2 = b2z; oc = 1; sb = 2; }
    else if (hh == 2) { w2 = W2d; bp2 = b2d; oc = 3; sb = 3; }
    else if (hh == 3) { w2 = W2r; bp2 = b2r; oc = 2; sb = 6; }
    else              { w2 = W2v; bp2 = b2v; oc = 2; sb = 8; }

    // first layer: channel wt for all 8 candidates; k vectorized by 4 (LDS.128)
    {
        int h = hh + 1;
        int hc = h*C + wt;
        float inv = gam[hc] / sqrtf(var[hc] + 1e-5f);
        float bb  = (b1[hc] - mu[hc]) * inv + bet[hc];
        const float* w = W1 + h*C*C + wt;
        float acc[GD_BATCH];
        #pragma unroll
        for (int c = 0; c < GD_BATCH; c++) acc[c] = 0.f;
        #pragma unroll 4
        for (int k4 = 0; k4 < C/4; k4++) {
            int kk = k4 * 4;
            float w0 = __ldg(w + (kk+0)*C);
            float w1v = __ldg(w + (kk+1)*C);
            float w2v = __ldg(w + (kk+2)*C);
            float w3 = __ldg(w + (kk+3)*C);
            #pragma unroll
            for (int c = 0; c < GD_BATCH; c++) {
                float4 xv = *reinterpret_cast<const float4*>(&xr[c][kk]);
                acc[c] += xv.x*w0 + xv.y*w1v + xv.z*w2v + xv.w*w3;
            }
        }
        #pragma unroll
        for (int c = 0; c < GD_BATCH; c++) hs[c][wt] = fmaxf(acc[c]*inv + bb, 0.f);
    }
    __syncthreads();

    // second layer: k-parallel, 16 lanes per candidate
    {
        int cand = wt >> 4, ln = wt & 15;
        float pc[3] = {0.f, 0.f, 0.f};
        #pragma unroll
        for (int q = 0; q < 8; q++) {
            int kk = ln + q*16;
            float hv = hs[cand][kk];
            #pragma unroll
            for (int col = 0; col < 3; col++)
                if (col < oc) pc[col] += hv * __ldg(w2 + kk*oc + col);
        }
        #pragma unroll
        for (int col = 0; col < 3; col++) {
            float v = pc[col];
            v += __shfl_xor_sync(0xffffffff, v, 1);
            v += __shfl_xor_sync(0xffffffff, v, 2);
            v += __shfl_xor_sync(0xffffffff, v, 4);
            v += __shfl_xor_sync(0xffffffff, v, 8);
            pc[col] = v;
        }
        if (ln == 0) {
            int e = e0 + cand;
            #pragma unroll
            for (int col = 0; col < 3; col++)
                if (col < oc) {
                    float a2 = pc[col] + __ldg(bp2 + col);
                    g_res[e*10 + sb + col] = (hh == 2) ? expf(a2) : a2;
                }
        }
    }
}

// ---------------- kernel 4b: per-candidate decode ----------------
__global__ void __launch_bounds__(256)
decode_kernel(const int* __restrict__ voxel_xy, float* __restrict__ out) {
    int e = blockIdx.x * 256 + threadIdx.x;
    if (e >= BATCH*TOPK) return;
    int b = e / TOPK, k = e % TOPK;
    float score = 1.f / (1.f + expf(-g_sel_score[e]));
    int   cls   = g_sel_cls[e];
    int   vox   = g_sel_vox[e];
    int   row   = b * NVOX + vox;
    const float* r = g_res + e*10;
    float vx = (float)voxel_xy[row*2 + 0];
    float vy = (float)voxel_xy[row*2 + 1];
    float xs = (vx + r[0]) * 0.6f - 54.0f;
    float ys = (vy + r[1]) * 0.6f - 54.0f;
    float cz = r[2];
    float ang = atan2f(r[7], r[6]);
    bool m = (xs >= -61.2f) && (xs <= 61.2f) &&
             (ys >= -61.2f) && (ys <= 61.2f) &&
             (cz >= -10.f)  && (cz <= 10.f)  && (score > 0.1f);
    float mf = m ? 1.f : 0.f;
    float* ob = out + (long)(b*TOPK + k) * 10;
    ob[0] = xs * mf;  ob[1] = ys * mf;  ob[2] = cz * mf;
    ob[3] = r[3] * mf; ob[4] = r[4] * mf; ob[5] = r[5] * mf;
    ob[6] = ang * mf; ob[7] = r[8] * mf; ob[8] = r[9] * mf;
    ob[9] = score * mf;
    int base = b*TOPK + k;
    out[BATCH*TOPK*10                 + base] = m ? (float)(cls + 1) : 0.f;
    out[BATCH*TOPK*10 + BATCH*TOPK   + base] = (float)(vox + b*NVOX);
    out[BATCH*TOPK*10 + 2*BATCH*TOPK + base] = mf;
}

// ---------------- host launcher ----------------
extern "C" void kernel_launch(void* const* d_in, const int* in_sizes, int n_in,
                              void* d_out, int out_size) {
    const float* feats    = (const float*)d_in[0];
    const int*   voxel_xy = (const int*)d_in[1];
    const float* W1  = (const float*)d_in[2];
    const float* b1  = (const float*)d_in[3];
    const float* gam = (const float*)d_in[4];
    const float* bet = (const float*)d_in[5];
    const float* mu  = (const float*)d_in[6];
    const float* var = (const float*)d_in[7];
    const float* W2_hm = (const float*)d_in[8];
    const float* b2_hm = (const float*)d_in[9];
    const float* W2_c  = (const float*)d_in[10];
    const float* b2_c  = (const float*)d_in[11];
    const float* W2_z  = (const float*)d_in[12];
    const float* b2_z  = (const float*)d_in[13];
    const float* W2_d  = (const float*)d_in[14];
    const float* b2_d  = (const float*)d_in[15];
    const float* W2_r  = (const float*)d_in[16];
    const float* b2_r  = (const float*)d_in[17];
    const float* W2_v  = (const float*)d_in[18];
    const float* b2_v  = (const float*)d_in[19];
    float* out = (float*)d_out;

    const int smem1 = SM_FLOATS * (int)sizeof(float);                 // 214528 B
    const int smem3 = CAND_PER_B * (int)sizeof(unsigned) + 512 * 8;
    cudaFuncSetAttribute(hm_kernel,          cudaFuncAttributeMaxDynamicSharedMemorySize, smem1);
    cudaFuncSetAttribute(global_topk_kernel, cudaFuncAttributeMaxDynamicSharedMemorySize, smem3);

    hm_kernel<<<HM_GRID, 256, smem1>>>(feats, W1, b1, gam, bet, mu, var, W2_hm, b2_hm);
    topk_chunk_kernel<<<BATCH * NCLS * NCHUNK, 512>>>();
    global_topk_kernel<<<BATCH, 1024, smem3>>>();
    head_kernel<<<5 * NGRP, 128>>>(feats, W1, b1, gam, bet, mu, var,
                                   W2_c, b2_c, W2_z, b2_z, W2_d, b2_d,
                                   W2_r, b2_r, W2_v, b2_v);
    decode_kernel<<<(BATCH*TOPK + 255)/256, 256>>>(voxel_xy, out);
}

// round 13
// speedup vs baseline: 1.2680x; 1.1998x over previous
#include <cuda_runtime.h>
#include <cuda_fp16.h>
#include <cstdint>

#define BATCH 4
#define NVOX  32768
#define NROWS (BATCH*NVOX)
#define C     128
#define NCLS  10
#define TOPK  500
#define NCHUNK 4
#define CHUNK  (NVOX/NCHUNK)          // 8192
#define CAND_PER_B (NCLS*NCHUNK*TOPK) // 20000
#define GD_BATCH 8
#define NGRP    (BATCH*TOPK/GD_BATCH) // 250

// hm mma.sync config (256 threads, 8 warps 4x2), fp16 split m16n8k16
#define HM_GRID 148
#define NTILES  (NROWS/128)           // 1024
#define XPAD 132
#define SM_XS  0                      // [128][132] X tile (16896)
#define SM_WP  16896                  // 16384: packed fp16 W fragments [8][16][32][4]
#define SM_W2  33280                  // 1280: [128][10]
#define SM_BF  34560                  // 128
#define SM_PO  34688                  // 2560: [2][128][10] (inv[] during prologue)
#define SM_FLOATS 37248               // -> 148992 bytes

// ---------------- device scratch ----------------
__device__ float g_hm[BATCH*NCLS*NVOX];            // raw logits
__device__ float g_cand_score[BATCH*CAND_PER_B];
__device__ int   g_cand_vox[BATCH*CAND_PER_B];
__device__ float g_sel_score[BATCH*TOPK];
__device__ int   g_sel_cls[BATCH*TOPK];
__device__ int   g_sel_vox[BATCH*TOPK];
__device__ float g_res[BATCH*TOPK*10];             // head outputs per candidate

__device__ __forceinline__ void mma_f16(float* d, const uint32_t* a, uint32_t b0, uint32_t b1) {
    asm volatile("mma.sync.aligned.m16n8k16.row.col.f32.f16.f16.f32 "
        "{%0,%1,%2,%3}, {%4,%5,%6,%7}, {%8,%9}, {%0,%1,%2,%3};"
        : "+f"(d[0]), "+f"(d[1]), "+f"(d[2]), "+f"(d[3])
        : "r"(a[0]), "r"(a[1]), "r"(a[2]), "r"(a[3]), "r"(b0), "r"(b1));
}
// split x,y into fp16 hi/lo pairs packed as half2 words
__device__ __forceinline__ void split_pack(float x, float y, uint32_t& hi, uint32_t& lo) {
    __half2 h = __floats2half2_rn(x, y);
    float2 hf = __half22float2(h);
    __half2 l = __floats2half2_rn(x - hf.x, y - hf.y);
    hi = *reinterpret_cast<uint32_t*>(&h);
    lo = *reinterpret_cast<uint32_t*>(&l);
}
__device__ __forceinline__ void cp_async16(uint32_t smem_addr, const void* gptr) {
    asm volatile("cp.async.cg.shared.global [%0], [%1], 16;" :: "r"(smem_addr), "l"(gptr));
}
#define CP_COMMIT() asm volatile("cp.async.commit_group;" ::: "memory")
#define CP_WAIT0()  asm volatile("cp.async.wait_group 0;" ::: "memory")

// ---------------- kernel 1: dense hm head, fp16 mma.sync 3-term split ----------------
__global__ void __launch_bounds__(256, 1)
hm_kernel(const float* __restrict__ feats,
          const float* __restrict__ W1, const float* __restrict__ b1,
          const float* __restrict__ gam, const float* __restrict__ bet,
          const float* __restrict__ mu,  const float* __restrict__ var,
          const float* __restrict__ W2, const float* __restrict__ b2) {
    extern __shared__ float sm[];
    float*  Xs  = sm + SM_XS;
    float*  Wp  = sm + SM_WP;
    float4* Wp4 = reinterpret_cast<float4*>(Wp);
    float*  W2s = sm + SM_W2;
    float*  bfs = sm + SM_BF;
    float*  po2 = sm + SM_PO;              // [2][128][10]; inv[] during prologue

    int tid  = threadIdx.x;
    int wid  = tid >> 5;
    int lane = tid & 31;
    int wm = wid >> 1, wn = wid & 1;       // warp tile: rows wm*32, cols wn*64

    uint32_t xs_base = (uint32_t)__cvta_generic_to_shared(Xs);
    int lr  = tid >> 5;
    int lc4 = (tid & 31) << 2;

    // issue async load of the FIRST tile (overlaps prologue)
    int tile0 = blockIdx.x;
    {
        int row0 = tile0 * 128;
        for (int r = lr; r < 128; r += 8)
            cp_async16(xs_base + (uint32_t)(r*XPAD + lc4)*4u,
                       feats + (long)(row0 + r)*C + lc4);
        CP_COMMIT();
    }

    // ---- prologue: fold BN for head 0, pack fp16 hi/lo fragments ----
    if (tid < C) {
        float inv = gam[tid] / sqrtf(var[tid] + 1e-5f);
        po2[tid] = inv;
        bfs[tid] = (b1[tid] - mu[tid]) * inv + bet[tid];
    }
    for (int i = tid; i < C*NCLS; i += 256) W2s[i] = W2[i];
    __syncthreads();
    // pack pairs of consecutive k for each c (avoids 16-bit write races)
    for (int i = tid; i < C*C/2; i += 256) {
        int c  = i & 127;
        int kp = i >> 7;                 // 0..63
        int k0 = kp * 2;
        float inv = po2[c];
        float v0 = W1[k0*C + c] * inv;
        float v1 = W1[(k0+1)*C + c] * inv;
        uint32_t hi, lo;
        split_pack(v0, v1, hi, lo);
        int kk  = k0 & 15;               // even
        int reg = (kk < 8) ? 0 : 1;
        int tig = (kk & 7) >> 1;
        int ks  = k0 >> 4;
        int nt  = c >> 3;
        int ln  = ((c & 7) << 2) | tig;
        int base = (((ks*16) + nt)*32 + ln) * 4;
        Wp[base + reg]     = __uint_as_float(hi);
        Wp[base + 2 + reg] = __uint_as_float(lo);
    }
    float b2r[NCLS];
    #pragma unroll
    for (int j = 0; j < NCLS; j++) b2r[j] = __ldg(b2 + j);

    for (int tile = tile0; tile < NTILES; tile += HM_GRID) {
        int row0 = tile * 128;
        CP_WAIT0();
        __syncthreads();        // Xs ready; po2/inv free after first pass

        float acc[2][8][4];
        #pragma unroll
        for (int mi = 0; mi < 2; mi++)
            #pragma unroll
            for (int ni = 0; ni < 8; ni++)
                #pragma unroll
                for (int q = 0; q < 4; q++) acc[mi][ni][q] = 0.f;

        int arow = wm*32 + (lane >> 2);
        int klo2 = (lane & 3) * 2;

        #pragma unroll
        for (int ks = 0; ks < 8; ks++) {
            int kA = ks*16 + klo2;
            uint32_t ahi[2][4], alo[2][4];
            #pragma unroll
            for (int mi = 0; mi < 2; mi++) {
                int r = arow + mi*16;
                float2 p0 = *reinterpret_cast<const float2*>(&Xs[r*XPAD + kA]);
                float2 p1 = *reinterpret_cast<const float2*>(&Xs[(r+8)*XPAD + kA]);
                float2 p2 = *reinterpret_cast<const float2*>(&Xs[r*XPAD + kA + 8]);
                float2 p3 = *reinterpret_cast<const float2*>(&Xs[(r+8)*XPAD + kA + 8]);
                split_pack(p0.x, p0.y, ahi[mi][0], alo[mi][0]);
                split_pack(p1.x, p1.y, ahi[mi][1], alo[mi][1]);
                split_pack(p2.x, p2.y, ahi[mi][2], alo[mi][2]);
                split_pack(p3.x, p3.y, ahi[mi][3], alo[mi][3]);
            }
            #pragma unroll
            for (int ni = 0; ni < 8; ni++) {
                int nt = wn*8 + ni;
                float4 v = Wp4[(ks*16 + nt)*32 + lane];
                uint32_t bh0 = __float_as_uint(v.x), bh1 = __float_as_uint(v.y);
                uint32_t bl0 = __float_as_uint(v.z), bl1 = __float_as_uint(v.w);
                #pragma unroll
                for (int mi = 0; mi < 2; mi++) {
                    mma_f16(acc[mi][ni], ahi[mi], bh0, bh1);
                    mma_f16(acc[mi][ni], ahi[mi], bl0, bl1);
                    mma_f16(acc[mi][ni], alo[mi], bh0, bh1);
                }
            }
        }
        __syncthreads();        // all warps done READING Xs

        // prefetch next tile while epilogue computes
        int ntile = tile + HM_GRID;
        if (ntile < NTILES) {
            int nrow0 = ntile * 128;
            for (int r = lr; r < 128; r += 8)
                cp_async16(xs_base + (uint32_t)(r*XPAD + lc4)*4u,
                           feats + (long)(nrow0 + r)*C + lc4);
        }
        CP_COMMIT();

        // ---- epilogue directly from accumulators ----
        float po[4][NCLS];
        #pragma unroll
        for (int s = 0; s < 4; s++)
            #pragma unroll
            for (int j = 0; j < NCLS; j++) po[s][j] = 0.f;

        #pragma unroll
        for (int ni = 0; ni < 8; ni++) {
            #pragma unroll
            for (int t = 0; t < 2; t++) {
                int c = wn*64 + ni*8 + 2*(lane & 3) + t;
                float bfc = bfs[c];
                float w2l[NCLS];
                #pragma unroll
                for (int j = 0; j < NCLS; j++) w2l[j] = W2s[c*NCLS + j];
                #pragma unroll
                for (int mi = 0; mi < 2; mi++) {
                    float h0 = fmaxf(acc[mi][ni][t]     + bfc, 0.f);
                    float h1 = fmaxf(acc[mi][ni][t + 2] + bfc, 0.f);
                    #pragma unroll
                    for (int j = 0; j < NCLS; j++) {
                        po[mi*2 + 0][j] += h0 * w2l[j];
                        po[mi*2 + 1][j] += h1 * w2l[j];
                    }
                }
            }
        }
        #pragma unroll
        for (int s = 0; s < 4; s++)
            #pragma unroll
            for (int j = 0; j < NCLS; j++) {
                float v = po[s][j];
                v += __shfl_xor_sync(0xffffffff, v, 1);
                v += __shfl_xor_sync(0xffffffff, v, 2);
                po[s][j] = v;
            }
        if ((lane & 3) == 0) {
            int rbase = wm*32 + (lane >> 2);
            #pragma unroll
            for (int s = 0; s < 4; s++) {
                int row = rbase + ((s & 1) ? 8 : 0) + ((s >> 1) ? 16 : 0);
                #pragma unroll
                for (int j = 0; j < NCLS; j++)
                    po2[(wn*128 + row)*NCLS + j] = po[s][j];
            }
        }
        __syncthreads();

        {
            int row = tid >> 1;
            int j0  = (tid & 1) * 5;
            int rrow = row0 + row;
            int b    = rrow >> 15;
            int v    = rrow & (NVOX - 1);
            #pragma unroll
            for (int j = 0; j < 5; j++) {
                float val = po2[row*NCLS + j0 + j] + po2[(128 + row)*NCLS + j0 + j] + b2r[j0 + j];
                g_hm[((long)(b*NCLS + j0 + j))*NVOX + v] = val;
            }
        }
        // loop-top CP_WAIT0 + syncthreads orders po2 reuse & Xs overwrite
    }
}

// ---------------- radix helpers ----------------
__device__ __forceinline__ unsigned key_of(float f) {
    unsigned u = __float_as_uint(f);
    return (u & 0x80000000u) ? ~u : (u | 0x80000000u);
}
__device__ __forceinline__ float float_of(unsigned k) {
    unsigned u = (k & 0x80000000u) ? (k & 0x7FFFFFFFu) : ~k;
    return __uint_as_float(u);
}
__device__ __forceinline__ void hist_add(int* hist, unsigned bin, bool act) {
    unsigned lm = __activemask();
    unsigned amask = __ballot_sync(lm, act);
    if (act) {
        unsigned peers = __match_any_sync(amask, bin);
        int leader = __ffs(peers) - 1;
        if ((int)(threadIdx.x & 31) == leader)
            atomicAdd(&hist[bin], __popc(peers));
    }
}
__device__ __forceinline__ void pick_bucket(int* hist, unsigned* sh_prefix,
                                            int* sh_rem, int shift) {
    __syncthreads();
    if (threadIdx.x < 32) {
        int lane = threadIdx.x;
        int b0 = lane * 8;
        int loc[8];
        int tot = 0;
        #pragma unroll
        for (int q = 0; q < 8; q++) { loc[q] = hist[b0 + q]; tot += loc[q]; }
        int s = tot;
        #pragma unroll
        for (int off = 1; off < 32; off <<= 1) {
            int t = __shfl_down_sync(0xffffffff, s, off);
            if (lane + off < 32) s += t;
        }
        int rem = *sh_rem;
        int cum = s - tot;
        #pragma unroll
        for (int q = 7; q >= 0; q--) {
            int prev = cum;
            cum += loc[q];
            if (cum >= rem && prev < rem) {
                *sh_rem    = rem - prev;
                *sh_prefix = *sh_prefix | ((unsigned)(b0 + q) << shift);
            }
        }
    }
    __syncthreads();
}
__constant__ unsigned c_mask[4] = {0u, 0xFF000000u, 0xFFFF0000u, 0xFFFFFF00u};

// ---------------- kernel 2: per-(b,cls,chunk) local top-500 ----------------
__global__ void __launch_bounds__(512)
topk_chunk_kernel() {
    __shared__ unsigned skey[CHUNK];
    __shared__ int hist[256];
    __shared__ unsigned sh_prefix;
    __shared__ int sh_rem, cgt, ceq;

    int blk = blockIdx.x;
    int bc  = blk >> 2, chunk = blk & 3;
    int tid = threadIdx.x, nt = blockDim.x;
    const float* src = g_hm + (long)bc * NVOX + chunk * CHUNK;

    for (int v = tid; v < CHUNK; v += nt) skey[v] = key_of(src[v]);
    if (tid == 0) { sh_prefix = 0; sh_rem = TOPK; }
    if (tid < 256) hist[tid] = 0;
    __syncthreads();

    #pragma unroll
    for (int p = 0; p < 4; p++) {
        int shift = 24 - 8*p;
        unsigned mask = c_mask[p], pref = sh_prefix;
        for (int v = tid; v < CHUNK; v += nt) {
            unsigned k = skey[v];
            hist_add(hist, (k >> shift) & 0xFF, (k & mask) == pref);
        }
        pick_bucket(hist, &sh_prefix, &sh_rem, shift);
        if (tid < 256) hist[tid] = 0;
        if (p == 3 && tid == 0) { cgt = 0; ceq = 0; }
        __syncthreads();
    }
    unsigned T = sh_prefix;
    int nEq = sh_rem;
    int nGt = TOPK - nEq;

    float* outS = g_cand_score + blk * TOPK;
    int*   outV = g_cand_vox   + blk * TOPK;
    int voff = chunk * CHUNK;
    for (int v = tid; v < CHUNK; v += nt) {
        unsigned k = skey[v];
        int slot = -1;
        if (k > T)       slot = atomicAdd(&cgt, 1);
        else if (k == T) { int q = atomicAdd(&ceq, 1); if (q < nEq) slot = nGt + q; }
        if (slot >= 0) { outS[slot] = src[v]; outV[slot] = voff + v; }
    }
}

// ---------------- kernel 3: per-batch top-500 of 20000 (rank-by-count) ----------------
__global__ void global_topk_kernel() {
    extern __shared__ unsigned sm3[];
    unsigned* skey = sm3;                                                // [20000]
    unsigned long long* sortb = (unsigned long long*)(sm3 + CAND_PER_B); // [512]
    __shared__ int hist[256];
    __shared__ unsigned sh_prefix;
    __shared__ int sh_rem, cgt, ceq;

    int b = blockIdx.x, tid = threadIdx.x, nt = blockDim.x;
    const float* cs = g_cand_score + (long)b * CAND_PER_B;

    for (int i = tid; i < CAND_PER_B; i += nt) skey[i] = key_of(cs[i]);
    if (tid < 512) sortb[tid] = 0ull;
    if (tid == 0) { sh_prefix = 0; sh_rem = TOPK; }
    if (tid < 256) hist[tid] = 0;
    __syncthreads();

    #pragma unroll
    for (int p = 0; p < 4; p++) {
        int shift = 24 - 8*p;
        unsigned mask = c_mask[p], pref = sh_prefix;
        for (int i = tid; i < CAND_PER_B; i += nt) {
            unsigned k = skey[i];
            hist_add(hist, (k >> shift) & 0xFF, (k & mask) == pref);
        }
        pick_bucket(hist, &sh_prefix, &sh_rem, shift);
        if (tid < 256) hist[tid] = 0;
        if (p == 3 && tid == 0) { cgt = 0; ceq = 0; }
        __syncthreads();
    }
    unsigned T = sh_prefix;
    int nEq = sh_rem;
    int nGt = TOPK - nEq;

    for (int i = tid; i < CAND_PER_B; i += nt) {
        unsigned k = skey[i];
        int slot = -1;
        if (k > T)       slot = atomicAdd(&cgt, 1);
        else if (k == T) { int q = atomicAdd(&ceq, 1); if (q < nEq) slot = nGt + q; }
        if (slot >= 0)
            sortb[slot] = (((unsigned long long)k) << 32) | (unsigned)i;
    }
    __syncthreads();

    if (tid < 512) {
        unsigned long long mine = sortb[tid];
        int rank = 0;
        for (int j = 0; j < 512; j++)
            rank += (sortb[j] > mine);
        if (mine != 0ull && rank < TOPK) {
            int idx = (int)(mine & 0xFFFFFFFFu);
            g_sel_score[b*TOPK + rank] = float_of((unsigned)(mine >> 32));
            g_sel_cls  [b*TOPK + rank] = idx / (NCHUNK*TOPK);
            g_sel_vox  [b*TOPK + rank] = g_cand_vox[(long)b*CAND_PER_B + idx];
        }
    }
}

// ---------------- kernel 4a: one (cand-group, head) per 128-thread block ----------------
__global__ void __launch_bounds__(128)
head_kernel(const float* __restrict__ feats,
            const float* __restrict__ W1, const float* __restrict__ b1,
            const float* __restrict__ gam, const float* __restrict__ bet,
            const float* __restrict__ mu,  const float* __restrict__ var,
            const float* __restrict__ W2c, const float* __restrict__ b2c,
            const float* __restrict__ W2z, const float* __restrict__ b2z,
            const float* __restrict__ W2d, const float* __restrict__ b2d,
            const float* __restrict__ W2r, const float* __restrict__ b2r,
            const float* __restrict__ W2v, const float* __restrict__ b2v) {
    int hh  = blockIdx.x / NGRP;       // 0..4 (same-head blocks adjacent -> L2-hot W1)
    int grp = blockIdx.x % NGRP;
    int e0  = grp * GD_BATCH;
    int wt  = threadIdx.x;
    __shared__ __align__(16) float xr[GD_BATCH][C];
    __shared__ __align__(16) float hs[GD_BATCH][C];
    __shared__ int svox[GD_BATCH];

    if (wt < GD_BATCH) svox[wt] = g_sel_vox[e0 + wt];
    __syncthreads();

    #pragma unroll
    for (int c = 0; c < GD_BATCH; c++) {
        int e = e0 + c;
        int row = (e / TOPK) * NVOX + svox[c];
        xr[c][wt] = __ldg(feats + (long)row*C + wt);
    }
    __syncthreads();

    const float* w2; const float* bp2; int oc, sb;
    if      (hh == 0) { w2 = W2c; bp2 = b2c; oc = 2; sb = 0; }
    else if (hh == 1) { w2 = W2z; bp2 = b2z; oc = 1; sb = 2; }
    else if (hh == 2) { w2 = W2d; bp2 = b2d; oc = 3; sb = 3; }
    else if (hh == 3) { w2 = W2r; bp2 = b2r; oc = 2; sb = 6; }
    else              { w2 = W2v; bp2 = b2v; oc = 2; sb = 8; }

    // first layer: channel wt for all 8 candidates; k vectorized by 4
    {
        int h = hh + 1;
        int hc = h*C + wt;
        float inv = gam[hc] / sqrtf(var[hc] + 1e-5f);
        float bb  = (b1[hc] - mu[hc]) * inv + bet[hc];
        const float* w = W1 + h*C*C + wt;
        float acc[GD_BATCH];
        #pragma unroll
        for (int c = 0; c < GD_BATCH; c++) acc[c] = 0.f;
        #pragma unroll 4
        for (int k4 = 0; k4 < C/4; k4++) {
            int kk = k4 * 4;
            float w0 = __ldg(w + (kk+0)*C);
            float w1v = __ldg(w + (kk+1)*C);
            float w2v = __ldg(w + (kk+2)*C);
            float w3 = __ldg(w + (kk+3)*C);
            #pragma unroll
            for (int c = 0; c < GD_BATCH; c++) {
                float4 xv = *reinterpret_cast<const float4*>(&xr[c][kk]);
                acc[c] += xv.x*w0 + xv.y*w1v + xv.z*w2v + xv.w*w3;
            }
        }
        #pragma unroll
        for (int c = 0; c < GD_BATCH; c++) hs[c][wt] = fmaxf(acc[c]*inv + bb, 0.f);
    }
    __syncthreads();

    // second layer: k-parallel, 16 lanes per candidate
    {
        int cand = wt >> 4, ln = wt & 15;
        float pc[3] = {0.f, 0.f, 0.f};
        #pragma unroll
        for (int q = 0; q < 8; q++) {
            int kk = ln + q*16;
            float hv = hs[cand][kk];
            #pragma unroll
            for (int col = 0; col < 3; col++)
                if (col < oc) pc[col] += hv * __ldg(w2 + kk*oc + col);
        }
        #pragma unroll
        for (int col = 0; col < 3; col++) {
            float v = pc[col];
            v += __shfl_xor_sync(0xffffffff, v, 1);
            v += __shfl_xor_sync(0xffffffff, v, 2);
            v += __shfl_xor_sync(0xffffffff, v, 4);
            v += __shfl_xor_sync(0xffffffff, v, 8);
            pc[col] = v;
        }
        if (ln == 0) {
            int e = e0 + cand;
            #pragma unroll
            for (int col = 0; col < 3; col++)
                if (col < oc) {
                    float a2 = pc[col] + __ldg(bp2 + col);
                    g_res[e*10 + sb + col] = (hh == 2) ? expf(a2) : a2;
                }
        }
    }
}

// ---------------- kernel 4b: per-candidate decode ----------------
__global__ void __launch_bounds__(256)
decode_kernel(const int* __restrict__ voxel_xy, float* __restrict__ out) {
    int e = blockIdx.x * 256 + threadIdx.x;
    if (e >= BATCH*TOPK) return;
    int b = e / TOPK, k = e % TOPK;
    float score = 1.f / (1.f + expf(-g_sel_score[e]));
    int   cls   = g_sel_cls[e];
    int   vox   = g_sel_vox[e];
    int   row   = b * NVOX + vox;
    const float* r = g_res + e*10;
    float vx = (float)voxel_xy[row*2 + 0];
    float vy = (float)voxel_xy[row*2 + 1];
    float xs = (vx + r[0]) * 0.6f - 54.0f;
    float ys = (vy + r[1]) * 0.6f - 54.0f;
    float cz = r[2];
    float ang = atan2f(r[7], r[6]);
    bool m = (xs >= -61.2f) && (xs <= 61.2f) &&
             (ys >= -61.2f) && (ys <= 61.2f) &&
             (cz >= -10.f)  && (cz <= 10.f)  && (score > 0.1f);
    float mf = m ? 1.f : 0.f;
    float* ob = out + (long)(b*TOPK + k) * 10;
    ob[0] = xs * mf;  ob[1] = ys * mf;  ob[2] = cz * mf;
    ob[3] = r[3] * mf; ob[4] = r[4] * mf; ob[5] = r[5] * mf;
    ob[6] = ang * mf; ob[7] = r[8] * mf; ob[8] = r[9] * mf;
    ob[9] = score * mf;
    int base = b*TOPK + k;
    out[BATCH*TOPK*10                 + base] = m ? (float)(cls + 1) : 0.f;
    out[BATCH*TOPK*10 + BATCH*TOPK   + base] = (float)(vox + b*NVOX);
    out[BATCH*TOPK*10 + 2*BATCH*TOPK + base] = mf;
}

// ---------------- host launcher ----------------
extern "C" void kernel_launch(void* const* d_in, const int* in_sizes, int n_in,
                              void* d_out, int out_size) {
    const float* feats    = (const float*)d_in[0];
    const int*   voxel_xy = (const int*)d_in[1];
    const float* W1  = (const float*)d_in[2];
    const float* b1  = (const float*)d_in[3];
    const float* gam = (const float*)d_in[4];
    const float* bet = (const float*)d_in[5];
    const float* mu  = (const float*)d_in[6];
    const float* var = (const float*)d_in[7];
    const float* W2_hm = (const float*)d_in[8];
    const float* b2_hm = (const float*)d_in[9];
    const float* W2_c  = (const float*)d_in[10];
    const float* b2_c  = (const float*)d_in[11];
    const float* W2_z  = (const float*)d_in[12];
    const float* b2_z  = (const float*)d_in[13];
    const float* W2_d  = (const float*)d_in[14];
    const float* b2_d  = (const float*)d_in[15];
    const float* W2_r  = (const float*)d_in[16];
    const float* b2_r  = (const float*)d_in[17];
    const float* W2_v  = (const float*)d_in[18];
    const float* b2_v  = (const float*)d_in[19];
    float* out = (float*)d_out;

    const int smem1 = SM_FLOATS * (int)sizeof(float);                 // 148992 B
    const int smem3 = CAND_PER_B * (int)sizeof(unsigned) + 512 * 8;
    cudaFuncSetAttribute(hm_kernel,          cudaFuncAttributeMaxDynamicSharedMemorySize, smem1);
    cudaFuncSetAttribute(global_topk_kernel, cudaFuncAttributeMaxDynamicSharedMemorySize, smem3);

    hm_kernel<<<HM_GRID, 256, smem1>>>(feats, W1, b1, gam, bet, mu, var, W2_hm, b2_hm);
    topk_chunk_kernel<<<BATCH * NCLS * NCHUNK, 512>>>();
    global_topk_kernel<<<BATCH, 1024, smem3>>>();
    head_kernel<<<5 * NGRP, 128>>>(feats, W1, b1, gam, bet, mu, var,
                                   W2_c, b2_c, W2_z, b2_z, W2_d, b2_d,
                                   W2_r, b2_r, W2_v, b2_v);
    decode_kernel<<<(BATCH*TOPK + 255)/256, 256>>>(voxel_xy, out);
}

// round 15
// speedup vs baseline: 1.2883x; 1.0160x over previous
#include <cuda_runtime.h>
#include <cuda_fp16.h>
#include <cstdint>

#define BATCH 4
#define NVOX  32768
#define NROWS (BATCH*NVOX)
#define C     128
#define NCLS  10
#define TOPK  500
#define NCHUNK 4
#define CHUNK  (NVOX/NCHUNK)          // 8192
#define CAND_PER_B (NCLS*NCHUNK*TOPK) // 20000
#define GD_BATCH 8
#define NGRP    (BATCH*TOPK/GD_BATCH) // 250

// hm mma.sync config: 64-row tiles, 256 threads / 8 warps (4 row-groups x 2 col-halves)
#define TROWS   64
#define HM_GRID 296
#define NTILES  (NROWS/TROWS)         // 2048
#define XPAD 132
#define SM_XS  0                      // [64][132] X tile = 8448 floats
#define SM_WP  8448                   // 16384 floats: packed fp16 W fragments [8][16][32][4]
#define SM_W2  24832                  // 1280: [128][10]
#define SM_BF  26112                  // 128
#define SM_PO  26240                  // 1280: [2][64][10] (inv[] during prologue)
#define SM_FLOATS 27520               // -> 110080 bytes (2 blocks/SM)

// ---------------- device scratch ----------------
__device__ float g_hm[BATCH*NCLS*NVOX];            // raw logits
__device__ float g_cand_score[BATCH*CAND_PER_B];
__device__ int   g_cand_vox[BATCH*CAND_PER_B];
__device__ float g_sel_score[BATCH*TOPK];
__device__ int   g_sel_cls[BATCH*TOPK];
__device__ int   g_sel_vox[BATCH*TOPK];
__device__ float g_res[BATCH*TOPK*10];             // head outputs per candidate

__device__ __forceinline__ void mma_f16(float* d, const uint32_t* a, uint32_t b0, uint32_t b1) {
    asm volatile("mma.sync.aligned.m16n8k16.row.col.f32.f16.f16.f32 "
        "{%0,%1,%2,%3}, {%4,%5,%6,%7}, {%8,%9}, {%0,%1,%2,%3};"
        : "+f"(d[0]), "+f"(d[1]), "+f"(d[2]), "+f"(d[3])
        : "r"(a[0]), "r"(a[1]), "r"(a[2]), "r"(a[3]), "r"(b0), "r"(b1));
}
// split x,y into fp16 hi/lo pairs packed as half2 words
__device__ __forceinline__ void split_pack(float x, float y, uint32_t& hi, uint32_t& lo) {
    __half2 h = __floats2half2_rn(x, y);
    float2 hf = __half22float2(h);
    __half2 l = __floats2half2_rn(x - hf.x, y - hf.y);
    hi = *reinterpret_cast<uint32_t*>(&h);
    lo = *reinterpret_cast<uint32_t*>(&l);
}
__device__ __forceinline__ void cp_async16(uint32_t smem_addr, const void* gptr) {
    asm volatile("cp.async.cg.shared.global [%0], [%1], 16;" :: "r"(smem_addr), "l"(gptr));
}
#define CP_COMMIT() asm volatile("cp.async.commit_group;" ::: "memory")
#define CP_WAIT0()  asm volatile("cp.async.wait_group 0;" ::: "memory")

// ---------------- kernel 1: dense hm head, fp16 mma.sync 3-term split, 64-row tiles ----------------
__global__ void __launch_bounds__(256, 2)
hm_kernel(const float* __restrict__ feats,
          const float* __restrict__ W1, const float* __restrict__ b1,
          const float* __restrict__ gam, const float* __restrict__ bet,
          const float* __restrict__ mu,  const float* __restrict__ var,
          const float* __restrict__ W2, const float* __restrict__ b2) {
    extern __shared__ float sm[];
    float*  Xs  = sm + SM_XS;
    float*  Wp  = sm + SM_WP;
    float4* Wp4 = reinterpret_cast<float4*>(Wp);
    float*  W2s = sm + SM_W2;
    float*  bfs = sm + SM_BF;
    float*  po2 = sm + SM_PO;              // [2][64][10]; inv[] during prologue

    int tid  = threadIdx.x;
    int lane = tid & 31;
    int wid  = tid >> 5;
    int wm = wid >> 1, wn = wid & 1;       // warp tile: rows wm*16, cols wn*64

    uint32_t xs_base = (uint32_t)__cvta_generic_to_shared(Xs);
    int lr  = tid >> 5;                    // 0..7
    int lc4 = (tid & 31) << 2;

    // issue async load of the FIRST tile (overlaps prologue)
    int tile0 = blockIdx.x;
    {
        int row0 = tile0 * TROWS;
        #pragma unroll
        for (int r = lr; r < TROWS; r += 8)
            cp_async16(xs_base + (uint32_t)(r*XPAD + lc4)*4u,
                       feats + (long)(row0 + r)*C + lc4);
        CP_COMMIT();
    }

    // ---- prologue: fold BN for head 0, pack fp16 hi/lo fragments ----
    if (tid < C) {
        float inv = gam[tid] / sqrtf(var[tid] + 1e-5f);
        po2[tid] = inv;
        bfs[tid] = (b1[tid] - mu[tid]) * inv + bet[tid];
    }
    for (int i = tid; i < C*NCLS; i += 256) W2s[i] = W2[i];
    __syncthreads();
    for (int i = tid; i < C*C/2; i += 256) {
        int c  = i & 127;
        int kp = i >> 7;                 // 0..63
        int k0 = kp * 2;
        float inv = po2[c];
        float v0 = W1[k0*C + c] * inv;
        float v1 = W1[(k0+1)*C + c] * inv;
        uint32_t hi, lo;
        split_pack(v0, v1, hi, lo);
        int kk  = k0 & 15;               // even
        int reg = (kk < 8) ? 0 : 1;
        int tig = (kk & 7) >> 1;
        int ks  = k0 >> 4;
        int nt  = c >> 3;
        int ln  = ((c & 7) << 2) | tig;
        int base = (((ks*16) + nt)*32 + ln) * 4;
        Wp[base + reg]     = __uint_as_float(hi);
        Wp[base + 2 + reg] = __uint_as_float(lo);
    }
    float b2r[NCLS];
    #pragma unroll
    for (int j = 0; j < NCLS; j++) b2r[j] = __ldg(b2 + j);

    for (int tile = tile0; tile < NTILES; tile += HM_GRID) {
        int row0 = tile * TROWS;
        CP_WAIT0();
        __syncthreads();        // Xs ready; po2/inv free after first pass

        float acc[8][4];
        #pragma unroll
        for (int ni = 0; ni < 8; ni++)
            #pragma unroll
            for (int q = 0; q < 4; q++) acc[ni][q] = 0.f;

        int arow = wm*16 + (lane >> 2);
        int klo2 = (lane & 3) * 2;

        #pragma unroll
        for (int ks = 0; ks < 8; ks++) {
            int kA = ks*16 + klo2;
            uint32_t ahi[4], alo[4];
            {
                float2 p0 = *reinterpret_cast<const float2*>(&Xs[arow*XPAD + kA]);
                float2 p1 = *reinterpret_cast<const float2*>(&Xs[(arow+8)*XPAD + kA]);
                float2 p2 = *reinterpret_cast<const float2*>(&Xs[arow*XPAD + kA + 8]);
                float2 p3 = *reinterpret_cast<const float2*>(&Xs[(arow+8)*XPAD + kA + 8]);
                split_pack(p0.x, p0.y, ahi[0], alo[0]);
                split_pack(p1.x, p1.y, ahi[1], alo[1]);
                split_pack(p2.x, p2.y, ahi[2], alo[2]);
                split_pack(p3.x, p3.y, ahi[3], alo[3]);
            }
            #pragma unroll
            for (int ni = 0; ni < 8; ni++) {
                int nt = wn*8 + ni;
                float4 v = Wp4[(ks*16 + nt)*32 + lane];
                uint32_t bh0 = __float_as_uint(v.x), bh1 = __float_as_uint(v.y);
                uint32_t bl0 = __float_as_uint(v.z), bl1 = __float_as_uint(v.w);
                mma_f16(acc[ni], ahi, bh0, bh1);
                mma_f16(acc[ni], ahi, bl0, bl1);
                mma_f16(acc[ni], alo, bh0, bh1);
            }
        }
        __syncthreads();        // all warps done READING Xs

        // prefetch next tile while epilogue computes
        int ntile = tile + HM_GRID;
        if (ntile < NTILES) {
            int nrow0 = ntile * TROWS;
            #pragma unroll
            for (int r = lr; r < TROWS; r += 8)
                cp_async16(xs_base + (uint32_t)(r*XPAD + lc4)*4u,
                           feats + (long)(nrow0 + r)*C + lc4);
        }
        CP_COMMIT();

        // ---- epilogue directly from accumulators ----
        float po[2][NCLS];
        #pragma unroll
        for (int s = 0; s < 2; s++)
            #pragma unroll
            for (int j = 0; j < NCLS; j++) po[s][j] = 0.f;

        #pragma unroll
        for (int ni = 0; ni < 8; ni++) {
            #pragma unroll
            for (int t = 0; t < 2; t++) {
                int c = wn*64 + ni*8 + 2*(lane & 3) + t;
                float bfc = bfs[c];
                float w2l[NCLS];
                #pragma unroll
                for (int j = 0; j < NCLS; j++) w2l[j] = W2s[c*NCLS + j];
                float h0 = fmaxf(acc[ni][t]     + bfc, 0.f);   // row arow
                float h1 = fmaxf(acc[ni][t + 2] + bfc, 0.f);   // row arow+8
                #pragma unroll
                for (int j = 0; j < NCLS; j++) {
                    po[0][j] += h0 * w2l[j];
                    po[1][j] += h1 * w2l[j];
                }
            }
        }
        #pragma unroll
        for (int s = 0; s < 2; s++)
            #pragma unroll
            for (int j = 0; j < NCLS; j++) {
                float v = po[s][j];
                v += __shfl_xor_sync(0xffffffff, v, 1);
                v += __shfl_xor_sync(0xffffffff, v, 2);
                po[s][j] = v;
            }
        if ((lane & 3) == 0) {
            int rbase = wm*16 + (lane >> 2);
            #pragma unroll
            for (int s = 0; s < 2; s++) {
                int row = rbase + s*8;
                #pragma unroll
                for (int j = 0; j < NCLS; j++)
                    po2[(wn*64 + row)*NCLS + j] = po[s][j];
            }
        }
        __syncthreads();

        if (tid < 128) {
            int row = tid >> 1;              // 0..63
            int j0  = (tid & 1) * 5;
            int rrow = row0 + row;
            int b    = rrow >> 15;
            int v    = rrow & (NVOX - 1);
            #pragma unroll
            for (int j = 0; j < 5; j++) {
                float val = po2[row*NCLS + j0 + j] + po2[(64 + row)*NCLS + j0 + j] + b2r[j0 + j];
                g_hm[((long)(b*NCLS + j0 + j))*NVOX + v] = val;
            }
        }
        // loop-top CP_WAIT0 + syncthreads orders po2 reuse & Xs overwrite
    }
}

// ---------------- radix helpers ----------------
__device__ __forceinline__ unsigned key_of(float f) {
    unsigned u = __float_as_uint(f);
    return (u & 0x80000000u) ? ~u : (u | 0x80000000u);
}
__device__ __forceinline__ float float_of(unsigned k) {
    unsigned u = (k & 0x80000000u) ? (k & 0x7FFFFFFFu) : ~k;
    return __uint_as_float(u);
}
__device__ __forceinline__ void hist_add(int* hist, unsigned bin, bool act) {
    unsigned lm = __activemask();
    unsigned amask = __ballot_sync(lm, act);
    if (act) {
        unsigned peers = __match_any_sync(amask, bin);
        int leader = __ffs(peers) - 1;
        if ((int)(threadIdx.x & 31) == leader)
            atomicAdd(&hist[bin], __popc(peers));
    }
}
__device__ __forceinline__ void pick_bucket(int* hist, unsigned* sh_prefix,
                                            int* sh_rem, int shift) {
    __syncthreads();
    if (threadIdx.x < 32) {
        int lane = threadIdx.x;
        int b0 = lane * 8;
        int loc[8];
        int tot = 0;
        #pragma unroll
        for (int q = 0; q < 8; q++) { loc[q] = hist[b0 + q]; tot += loc[q]; }
        int s = tot;
        #pragma unroll
        for (int off = 1; off < 32; off <<= 1) {
            int t = __shfl_down_sync(0xffffffff, s, off);
            if (lane + off < 32) s += t;
        }
        int rem = *sh_rem;
        int cum = s - tot;
        #pragma unroll
        for (int q = 7; q >= 0; q--) {
            int prev = cum;
            cum += loc[q];
            if (cum >= rem && prev < rem) {
                *sh_rem    = rem - prev;
                *sh_prefix = *sh_prefix | ((unsigned)(b0 + q) << shift);
            }
        }
    }
    __syncthreads();
}
__constant__ unsigned c_mask[4] = {0u, 0xFF000000u, 0xFFFF0000u, 0xFFFFFF00u};

// ---------------- kernel 2: per-(b,cls,chunk) local top-500 ----------------
__global__ void __launch_bounds__(512)
topk_chunk_kernel() {
    __shared__ unsigned skey[CHUNK];
    __shared__ int hist[256];
    __shared__ unsigned sh_prefix;
    __shared__ int sh_rem, cgt, ceq;

    int blk = blockIdx.x;
    int bc  = blk >> 2, chunk = blk & 3;
    int tid = threadIdx.x, nt = blockDim.x;
    const float* src = g_hm + (long)bc * NVOX + chunk * CHUNK;

    for (int v = tid; v < CHUNK; v += nt) skey[v] = key_of(src[v]);
    if (tid == 0) { sh_prefix = 0; sh_rem = TOPK; }
    if (tid < 256) hist[tid] = 0;
    __syncthreads();

    #pragma unroll
    for (int p = 0; p < 4; p++) {
        int shift = 24 - 8*p;
        unsigned mask = c_mask[p], pref = sh_prefix;
        for (int v = tid; v < CHUNK; v += nt) {
            unsigned k = skey[v];
            hist_add(hist, (k >> shift) & 0xFF, (k & mask) == pref);
        }
        pick_bucket(hist, &sh_prefix, &sh_rem, shift);
        if (tid < 256) hist[tid] = 0;
        if (p == 3 && tid == 0) { cgt = 0; ceq = 0; }
        __syncthreads();
    }
    unsigned T = sh_prefix;
    int nEq = sh_rem;
    int nGt = TOPK - nEq;

    float* outS = g_cand_score + blk * TOPK;
    int*   outV = g_cand_vox   + blk * TOPK;
    int voff = chunk * CHUNK;
    for (int v = tid; v < CHUNK; v += nt) {
        unsigned k = skey[v];
        int slot = -1;
        if (k > T)       slot = atomicAdd(&cgt, 1);
        else if (k == T) { int q = atomicAdd(&ceq, 1); if (q < nEq) slot = nGt + q; }
        if (slot >= 0) { outS[slot] = src[v]; outV[slot] = voff + v; }
    }
}

// ---------------- kernel 3: per-batch top-500 of 20000 (rank-by-count) ----------------
__global__ void global_topk_kernel() {
    extern __shared__ unsigned sm3[];
    unsigned* skey = sm3;                                                // [20000]
    unsigned long long* sortb = (unsigned long long*)(sm3 + CAND_PER_B); // [512]
    __shared__ int hist[256];
    __shared__ unsigned sh_prefix;
    __shared__ int sh_rem, cgt, ceq;

    int b = blockIdx.x, tid = threadIdx.x, nt = blockDim.x;
    const float* cs = g_cand_score + (long)b * CAND_PER_B;

    for (int i = tid; i < CAND_PER_B; i += nt) skey[i] = key_of(cs[i]);
    if (tid < 512) sortb[tid] = 0ull;
    if (tid == 0) { sh_prefix = 0; sh_rem = TOPK; }
    if (tid < 256) hist[tid] = 0;
    __syncthreads();

    #pragma unroll
    for (int p = 0; p < 4; p++) {
        int shift = 24 - 8*p;
        unsigned mask = c_mask[p], pref = sh_prefix;
        for (int i = tid; i < CAND_PER_B; i += nt) {
            unsigned k = skey[i];
            hist_add(hist, (k >> shift) & 0xFF, (k & mask) == pref);
        }
        pick_bucket(hist, &sh_prefix, &sh_rem, shift);
        if (tid < 256) hist[tid] = 0;
        if (p == 3 && tid == 0) { cgt = 0; ceq = 0; }
        __syncthreads();
    }
    unsigned T = sh_prefix;
    int nEq = sh_rem;
    int nGt = TOPK - nEq;

    for (int i = tid; i < CAND_PER_B; i += nt) {
        unsigned k = skey[i];
        int slot = -1;
        if (k > T)       slot = atomicAdd(&cgt, 1);
        else if (k == T) { int q = atomicAdd(&ceq, 1); if (q < nEq) slot = nGt + q; }
        if (slot >= 0)
            sortb[slot] = (((unsigned long long)k) << 32) | (unsigned)i;
    }
    __syncthreads();

    if (tid < 512) {
        unsigned long long mine = sortb[tid];
        int rank = 0;
        for (int j = 0; j < 512; j++)
            rank += (sortb[j] > mine);
        if (mine != 0ull && rank < TOPK) {
            int idx = (int)(mine & 0xFFFFFFFFu);
            g_sel_score[b*TOPK + rank] = float_of((unsigned)(mine >> 32));
            g_sel_cls  [b*TOPK + rank] = idx / (NCHUNK*TOPK);
            g_sel_vox  [b*TOPK + rank] = g_cand_vox[(long)b*CAND_PER_B + idx];
        }
    }
}

// ---------------- kernel 4a: one (cand-group, head) per 128-thread block ----------------
__global__ void __launch_bounds__(128)
head_kernel(const float* __restrict__ feats,
            const float* __restrict__ W1, const float* __restrict__ b1,
            const float* __restrict__ gam, const float* __restrict__ bet,
            const float* __restrict__ mu,  const float* __restrict__ var,
            const float* __restrict__ W2c, const float* __restrict__ b2c,
            const float* __restrict__ W2z, const float* __restrict__ b2z,
            const float* __restrict__ W2d, const float* __restrict__ b2d,
            const float* __restrict__ W2r, const float* __restrict__ b2r,
            const float* __restrict__ W2v, const float* __restrict__ b2v) {
    int hh  = blockIdx.x / NGRP;       // 0..4 (same-head blocks adjacent -> L2-hot W1)
    int grp = blockIdx.x % NGRP;
    int e0  = grp * GD_BATCH;
    int wt  = threadIdx.x;
    __shared__ __align__(16) float xr[GD_BATCH][C];
    __shared__ __align__(16) float hs[GD_BATCH][C];
    __shared__ int svox[GD_BATCH];

    if (wt < GD_BATCH) svox[wt] = g_sel_vox[e0 + wt];
    __syncthreads();

    #pragma unroll
    for (int c = 0; c < GD_BATCH; c++) {
        int e = e0 + c;
        int row = (e / TOPK) * NVOX + svox[c];
        xr[c][wt] = __ldg(feats + (long)row*C + wt);
    }
    __syncthreads();

    const float* w2; const float* bp2; int oc, sb;
    if      (hh == 0) { w2 = W2c; bp2 = b2c; oc = 2; sb = 0; }
    else if (hh == 1) { w2 = W2z; bp2 = b2z; oc = 1; sb = 2; }
    else if (hh == 2) { w2 = W2d; bp2 = b2d; oc = 3; sb = 3; }
    else if (hh == 3) { w2 = W2r; bp2 = b2r; oc = 2; sb = 6; }
    else              { w2 = W2v; bp2 = b2v; oc = 2; sb = 8; }

    // first layer: channel wt for all 8 candidates; k vectorized by 4
    {
        int h = hh + 1;
        int hc = h*C + wt;
        float inv = gam[hc] / sqrtf(var[hc] + 1e-5f);
        float bb  = (b1[hc] - mu[hc]) * inv + bet[hc];
        const float* w = W1 + h*C*C + wt;
        float acc[GD_BATCH];
        #pragma unroll
        for (int c = 0; c < GD_BATCH; c++) acc[c] = 0.f;
        #pragma unroll 4
        for (int k4 = 0; k4 < C/4; k4++) {
            int kk = k4 * 4;
            float w0 = __ldg(w + (kk+0)*C);
            float w1v = __ldg(w + (kk+1)*C);
            float w2v = __ldg(w + (kk+2)*C);
            float w3 = __ldg(w + (kk+3)*C);
            #pragma unroll
            for (int c = 0; c < GD_BATCH; c++) {
                float4 xv = *reinterpret_cast<const float4*>(&xr[c][kk]);
                acc[c] += xv.x*w0 + xv.y*w1v + xv.z*w2v + xv.w*w3;
            }
        }
        #pragma unroll
        for (int c = 0; c < GD_BATCH; c++) hs[c][wt] = fmaxf(acc[c]*inv + bb, 0.f);
    }
    __syncthreads();

    // second layer: k-parallel, 16 lanes per candidate
    {
        int cand = wt >> 4, ln = wt & 15;
        float pc[3] = {0.f, 0.f, 0.f};
        #pragma unroll
        for (int q = 0; q < 8; q++) {
            int kk = ln + q*16;
            float hv = hs[cand][kk];
            #pragma unroll
            for (int col = 0; col < 3; col++)
                if (col < oc) pc[col] += hv * __ldg(w2 + kk*oc + col);
        }
        #pragma unroll
        for (int col = 0; col < 3; col++) {
            float v = pc[col];
            v += __shfl_xor_sync(0xffffffff, v, 1);
            v += __shfl_xor_sync(0xffffffff, v, 2);
            v += __shfl_xor_sync(0xffffffff, v, 4);
            v += __shfl_xor_sync(0xffffffff, v, 8);
            pc[col] = v;
        }
        if (ln == 0) {
            int e = e0 + cand;
            #pragma unroll
            for (int col = 0; col < 3; col++)
                if (col < oc) {
                    float a2 = pc[col] + __ldg(bp2 + col);
                    g_res[e*10 + sb + col] = (hh == 2) ? expf(a2) : a2;
                }
        }
    }
}

// ---------------- kernel 4b: per-candidate decode ----------------
__global__ void __launch_bounds__(256)
decode_kernel(const int* __restrict__ voxel_xy, float* __restrict__ out) {
    int e = blockIdx.x * 256 + threadIdx.x;
    if (e >= BATCH*TOPK) return;
    int b = e / TOPK, k = e % TOPK;
    float score = 1.f / (1.f + expf(-g_sel_score[e]));
    int   cls   = g_sel_cls[e];
    int   vox   = g_sel_vox[e];
    int   row   = b * NVOX + vox;
    const float* r = g_res + e*10;
    float vx = (float)voxel_xy[row*2 + 0];
    float vy = (float)voxel_xy[row*2 + 1];
    float xs = (vx + r[0]) * 0.6f - 54.0f;
    float ys = (vy + r[1]) * 0.6f - 54.0f;
    float cz = r[2];
    float ang = atan2f(r[7], r[6]);
    bool m = (xs >= -61.2f) && (xs <= 61.2f) &&
             (ys >= -61.2f) && (ys <= 61.2f) &&
             (cz >= -10.f)  && (cz <= 10.f)  && (score > 0.1f);
    float mf = m ? 1.f : 0.f;
    float* ob = out + (long)(b*TOPK + k) * 10;
    ob[0] = xs * mf;  ob[1] = ys * mf;  ob[2] = cz * mf;
    ob[3] = r[3] * mf; ob[4] = r[4] * mf; ob[5] = r[5] * mf;
    ob[6] = ang * mf; ob[7] = r[8] * mf; ob[8] = r[9] * mf;
    ob[9] = score * mf;
    int base = b*TOPK + k;
    out[BATCH*TOPK*10                 + base] = m ? (float)(cls + 1) : 0.f;
    out[BATCH*TOPK*10 + BATCH*TOPK   + base] = (float)(vox + b*NVOX);
    out[BATCH*TOPK*10 + 2*BATCH*TOPK + base] = mf;
}

// ---------------- host launcher ----------------
extern "C" void kernel_launch(void* const* d_in, const int* in_sizes, int n_in,
                              void* d_out, int out_size) {
    const float* feats    = (const float*)d_in[0];
    const int*   voxel_xy = (const int*)d_in[1];
    const float* W1  = (const float*)d_in[2];
    const float* b1  = (const float*)d_in[3];
    const float* gam = (const float*)d_in[4];
    const float* bet = (const float*)d_in[5];
    const float* mu  = (const float*)d_in[6];
    const float* var = (const float*)d_in[7];
    const float* W2_hm = (const float*)d_in[8];
    const float* b2_hm = (const float*)d_in[9];
    const float* W2_c  = (const float*)d_in[10];
    const float* b2_c  = (const float*)d_in[11];
    const float* W2_z  = (const float*)d_in[12];
    const float* b2_z  = (const float*)d_in[13];
    const float* W2_d  = (const float*)d_in[14];
    const float* b2_d  = (const float*)d_in[15];
    const float* W2_r  = (const float*)d_in[16];
    const float* b2_r  = (const float*)d_in[17];
    const float* W2_v  = (const float*)d_in[18];
    const float* b2_v  = (const float*)d_in[19];
    float* out = (float*)d_out;

    const int smem1 = SM_FLOATS * (int)sizeof(float);                 // 110080 B
    const int smem3 = CAND_PER_B * (int)sizeof(unsigned) + 512 * 8;
    cudaFuncSetAttribute(hm_kernel,          cudaFuncAttributeMaxDynamicSharedMemorySize, smem1);
    cudaFuncSetAttribute(global_topk_kernel, cudaFuncAttributeMaxDynamicSharedMemorySize, smem3);

    hm_kernel<<<HM_GRID, 256, smem1>>>(feats, W1, b1, gam, bet, mu, var, W2_hm, b2_hm);
    topk_chunk_kernel<<<BATCH * NCLS * NCHUNK, 512>>>();
    global_topk_kernel<<<BATCH, 1024, smem3>>>();
    head_kernel<<<5 * NGRP, 128>>>(feats, W1, b1, gam, bet, mu, var,
                                   W2_c, b2_c, W2_z, b2_z, W2_d, b2_d,
                                   W2_r, b2_r, W2_v, b2_v);
    decode_kernel<<<(BATCH*TOPK + 255)/256, 256>>>(voxel_xy, out);
}

// round 16
// speedup vs baseline: 1.3149x; 1.0206x over previous
#include <cuda_runtime.h>
#include <cuda_fp16.h>
#include <cstdint>

#define BATCH 4
#define NVOX  32768
#define NROWS (BATCH*NVOX)
#define C     128
#define NCLS  10
#define TOPK  500
#define NCHUNK 4
#define CHUNK  (NVOX/NCHUNK)          // 8192
#define CAND_PER_B (NCLS*NCHUNK*TOPK) // 20000
#define GD_BATCH 8
#define NGRP    (BATCH*TOPK/GD_BATCH) // 250

// hm mma.sync config: 64-row tiles, 256 threads / 8 warps (4 row-groups x 2 col-halves)
#define TROWS   64
#define HM_GRID 296
#define NTILES  (NROWS/TROWS)         // 2048
// smem layout (in floats/uint32 words):
//   [0, 4352)      hi plane  uint32 [64][68]  (64 data half2 + 4 pad per row)
//   [4352, 8704)   lo plane  uint32 [64][68]
//   [8704, 25088)  packed fp16 W fragments [8][16][32][4]
//   [25088, 26368) W2s [128][10]
//   [26368, 26496) bfs [128]
//   [26496, 27776) po2 [2][64][10] (inv[] during prologue)
#define SM_HI  0
#define SM_LO  4352
#define SM_WP  8704
#define SM_W2  25088
#define SM_BF  26368
#define SM_PO  26496
#define SM_FLOATS 27776               // -> 111104 bytes (2 blocks/SM)

// ---------------- device scratch ----------------
__device__ float g_hm[BATCH*NCLS*NVOX];            // raw logits
__device__ float g_cand_score[BATCH*CAND_PER_B];
__device__ int   g_cand_vox[BATCH*CAND_PER_B];
__device__ float g_sel_score[BATCH*TOPK];
__device__ int   g_sel_cls[BATCH*TOPK];
__device__ int   g_sel_vox[BATCH*TOPK];
__device__ float g_res[BATCH*TOPK*10];             // head outputs per candidate

__device__ __forceinline__ void mma_f16(float* d, const uint32_t* a, uint32_t b0, uint32_t b1) {
    asm volatile("mma.sync.aligned.m16n8k16.row.col.f32.f16.f16.f32 "
        "{%0,%1,%2,%3}, {%4,%5,%6,%7}, {%8,%9}, {%0,%1,%2,%3};"
        : "+f"(d[0]), "+f"(d[1]), "+f"(d[2]), "+f"(d[3])
        : "r"(a[0]), "r"(a[1]), "r"(a[2]), "r"(a[3]), "r"(b0), "r"(b1));
}
__device__ __forceinline__ void ldmatrix_x4(uint32_t* r, uint32_t addr) {
    asm volatile("ldmatrix.sync.aligned.m8n8.x4.shared.b16 {%0,%1,%2,%3}, [%4];"
        : "=r"(r[0]), "=r"(r[1]), "=r"(r[2]), "=r"(r[3]) : "r"(addr));
}
// split x,y into fp16 hi/lo pairs packed as half2 words
__device__ __forceinline__ void split_pack(float x, float y, uint32_t& hi, uint32_t& lo) {
    __half2 h = __floats2half2_rn(x, y);
    float2 hf = __half22float2(h);
    __half2 l = __floats2half2_rn(x - hf.x, y - hf.y);
    hi = *reinterpret_cast<uint32_t*>(&h);
    lo = *reinterpret_cast<uint32_t*>(&l);
}

// ---------------- kernel 1: dense hm head, fp16 split + ldmatrix A planes ----------------
__global__ void __launch_bounds__(256, 2)
hm_kernel(const float* __restrict__ feats,
          const float* __restrict__ W1, const float* __restrict__ b1,
          const float* __restrict__ gam, const float* __restrict__ bet,
          const float* __restrict__ mu,  const float* __restrict__ var,
          const float* __restrict__ W2, const float* __restrict__ b2) {
    extern __shared__ float sm[];
    uint32_t* hip = reinterpret_cast<uint32_t*>(sm) + SM_HI;   // [64][68]
    uint32_t* lop = reinterpret_cast<uint32_t*>(sm) + SM_LO;
    float*  Wp  = sm + SM_WP;
    float4* Wp4 = reinterpret_cast<float4*>(Wp);
    float*  W2s = sm + SM_W2;
    float*  bfs = sm + SM_BF;
    float*  po2 = sm + SM_PO;              // [2][64][10]; inv[] during prologue

    int tid  = threadIdx.x;
    int lane = tid & 31;
    int wid  = tid >> 5;
    int wm = wid >> 1, wn = wid & 1;       // warp tile: rows wm*16, cols wn*64

    uint32_t smbase = (uint32_t)__cvta_generic_to_shared(sm);

    // ---- prologue: fold BN for head 0, pack fp16 hi/lo fragments ----
    if (tid < C) {
        float inv = gam[tid] / sqrtf(var[tid] + 1e-5f);
        po2[tid] = inv;
        bfs[tid] = (b1[tid] - mu[tid]) * inv + bet[tid];
    }
    for (int i = tid; i < C*NCLS; i += 256) W2s[i] = W2[i];
    __syncthreads();
    for (int i = tid; i < C*C/2; i += 256) {
        int c  = i & 127;
        int kp = i >> 7;                 // 0..63
        int k0 = kp * 2;
        float inv = po2[c];
        float v0 = W1[k0*C + c] * inv;
        float v1 = W1[(k0+1)*C + c] * inv;
        uint32_t hi, lo;
        split_pack(v0, v1, hi, lo);
        int kk  = k0 & 15;               // even
        int reg = (kk < 8) ? 0 : 1;
        int tig = (kk & 7) >> 1;
        int ks  = k0 >> 4;
        int nt  = c >> 3;
        int ln  = ((c & 7) << 2) | tig;
        int base = (((ks*16) + nt)*32 + ln) * 4;
        Wp[base + reg]     = __uint_as_float(hi);
        Wp[base + 2 + reg] = __uint_as_float(lo);
    }
    float b2r[NCLS];
    #pragma unroll
    for (int j = 0; j < NCLS; j++) b2r[j] = __ldg(b2 + j);

    // per-lane ldmatrix addresses (hi plane; lo = +SM_LO words)
    int grp  = lane >> 3;
    int lrow = wm*16 + (lane & 7) + ((grp & 1) << 3);
    int kboff = (grp >> 1) * 4;                       // uint32 words
    uint32_t a_hi0 = smbase + (uint32_t)(SM_HI + lrow*68 + kboff) * 4u;
    uint32_t a_lo0 = smbase + (uint32_t)(SM_LO + lrow*68 + kboff) * 4u;

    for (int tile = blockIdx.x; tile < NTILES; tile += HM_GRID) {
        int row0 = tile * TROWS;

        // ---- load + convert X tile into fp16 hi/lo planes ----
        for (int i = tid; i < TROWS*32; i += 256) {
            int r  = i >> 5;
            int c4 = (i & 31) << 2;
            float4 f = *reinterpret_cast<const float4*>(feats + (long)(row0 + r)*C + c4);
            uint32_t h0, l0, h1, l1;
            split_pack(f.x, f.y, h0, l0);
            split_pack(f.z, f.w, h1, l1);
            int w = r*68 + (c4 >> 1);
            *reinterpret_cast<uint2*>(&hip[w]) = make_uint2(h0, h1);
            *reinterpret_cast<uint2*>(&lop[w]) = make_uint2(l0, l1);
        }
        __syncthreads();        // planes ready; Wp ready (first iter)

        float acc[8][4];
        #pragma unroll
        for (int ni = 0; ni < 8; ni++)
            #pragma unroll
            for (int q = 0; q < 4; q++) acc[ni][q] = 0.f;

        #pragma unroll
        for (int ks = 0; ks < 8; ks++) {
            uint32_t ahi[4], alo[4];
            ldmatrix_x4(ahi, a_hi0 + (uint32_t)(ks*8)*4u);
            ldmatrix_x4(alo, a_lo0 + (uint32_t)(ks*8)*4u);
            #pragma unroll
            for (int ni = 0; ni < 8; ni++) {
                int nt = wn*8 + ni;
                float4 v = Wp4[(ks*16 + nt)*32 + lane];
                uint32_t bh0 = __float_as_uint(v.x), bh1 = __float_as_uint(v.y);
                uint32_t bl0 = __float_as_uint(v.z), bl1 = __float_as_uint(v.w);
                mma_f16(acc[ni], ahi, bh0, bh1);
                mma_f16(acc[ni], ahi, bl0, bl1);
                mma_f16(acc[ni], alo, bh0, bh1);
            }
        }
        __syncthreads();        // all warps done READING planes

        // ---- epilogue directly from accumulators ----
        float po[2][NCLS];
        #pragma unroll
        for (int s = 0; s < 2; s++)
            #pragma unroll
            for (int j = 0; j < NCLS; j++) po[s][j] = 0.f;

        #pragma unroll
        for (int ni = 0; ni < 8; ni++) {
            #pragma unroll
            for (int t = 0; t < 2; t++) {
                int c = wn*64 + ni*8 + 2*(lane & 3) + t;
                float bfc = bfs[c];
                float w2l[NCLS];
                #pragma unroll
                for (int j = 0; j < NCLS; j++) w2l[j] = W2s[c*NCLS + j];
                float h0 = fmaxf(acc[ni][t]     + bfc, 0.f);   // row lrow-group base
                float h1 = fmaxf(acc[ni][t + 2] + bfc, 0.f);   // row +8
                #pragma unroll
                for (int j = 0; j < NCLS; j++) {
                    po[0][j] += h0 * w2l[j];
                    po[1][j] += h1 * w2l[j];
                }
            }
        }
        #pragma unroll
        for (int s = 0; s < 2; s++)
            #pragma unroll
            for (int j = 0; j < NCLS; j++) {
                float v = po[s][j];
                v += __shfl_xor_sync(0xffffffff, v, 1);
                v += __shfl_xor_sync(0xffffffff, v, 2);
                po[s][j] = v;
            }
        if ((lane & 3) == 0) {
            int rbase = wm*16 + (lane >> 2);
            #pragma unroll
            for (int s = 0; s < 2; s++) {
                int row = rbase + s*8;
                #pragma unroll
                for (int j = 0; j < NCLS; j++)
                    po2[(wn*64 + row)*NCLS + j] = po[s][j];
            }
        }
        __syncthreads();

        if (tid < 128) {
            int row = tid >> 1;              // 0..63
            int j0  = (tid & 1) * 5;
            int rrow = row0 + row;
            int b    = rrow >> 15;
            int v    = rrow & (NVOX - 1);
            #pragma unroll
            for (int j = 0; j < 5; j++) {
                float val = po2[row*NCLS + j0 + j] + po2[(64 + row)*NCLS + j0 + j] + b2r[j0 + j];
                g_hm[((long)(b*NCLS + j0 + j))*NVOX + v] = val;
            }
        }
        __syncthreads();        // po2 read done; planes free for next conv
    }
}

// ---------------- radix helpers ----------------
__device__ __forceinline__ unsigned key_of(float f) {
    unsigned u = __float_as_uint(f);
    return (u & 0x80000000u) ? ~u : (u | 0x80000000u);
}
__device__ __forceinline__ float float_of(unsigned k) {
    unsigned u = (k & 0x80000000u) ? (k & 0x7FFFFFFFu) : ~k;
    return __uint_as_float(u);
}
__device__ __forceinline__ void hist_add(int* hist, unsigned bin, bool act) {
    unsigned lm = __activemask();
    unsigned amask = __ballot_sync(lm, act);
    if (act) {
        unsigned peers = __match_any_sync(amask, bin);
        int leader = __ffs(peers) - 1;
        if ((int)(threadIdx.x & 31) == leader)
            atomicAdd(&hist[bin], __popc(peers));
    }
}
__device__ __forceinline__ void pick_bucket(int* hist, unsigned* sh_prefix,
                                            int* sh_rem, int shift) {
    __syncthreads();
    if (threadIdx.x < 32) {
        int lane = threadIdx.x;
        int b0 = lane * 8;
        int loc[8];
        int tot = 0;
        #pragma unroll
        for (int q = 0; q < 8; q++) { loc[q] = hist[b0 + q]; tot += loc[q]; }
        int s = tot;
        #pragma unroll
        for (int off = 1; off < 32; off <<= 1) {
            int t = __shfl_down_sync(0xffffffff, s, off);
            if (lane + off < 32) s += t;
        }
        int rem = *sh_rem;
        int cum = s - tot;
        #pragma unroll
        for (int q = 7; q >= 0; q--) {
            int prev = cum;
            cum += loc[q];
            if (cum >= rem && prev < rem) {
                *sh_rem    = rem - prev;
                *sh_prefix = *sh_prefix | ((unsigned)(b0 + q) << shift);
            }
        }
    }
    __syncthreads();
}
__constant__ unsigned c_mask[4] = {0u, 0xFF000000u, 0xFFFF0000u, 0xFFFFFF00u};

// ---------------- kernel 2: per-(b,cls,chunk) local top-500 ----------------
__global__ void __launch_bounds__(512)
topk_chunk_kernel() {
    __shared__ unsigned skey[CHUNK];
    __shared__ int hist[256];
    __shared__ unsigned sh_prefix;
    __shared__ int sh_rem, cgt, ceq;

    int blk = blockIdx.x;
    int bc  = blk >> 2, chunk = blk & 3;
    int tid = threadIdx.x, nt = blockDim.x;
    const float* src = g_hm + (long)bc * NVOX + chunk * CHUNK;

    for (int v = tid; v < CHUNK; v += nt) skey[v] = key_of(src[v]);
    if (tid == 0) { sh_prefix = 0; sh_rem = TOPK; }
    if (tid < 256) hist[tid] = 0;
    __syncthreads();

    #pragma unroll
    for (int p = 0; p < 4; p++) {
        int shift = 24 - 8*p;
        unsigned mask = c_mask[p], pref = sh_prefix;
        for (int v = tid; v < CHUNK; v += nt) {
            unsigned k = skey[v];
            hist_add(hist, (k >> shift) & 0xFF, (k & mask) == pref);
        }
        pick_bucket(hist, &sh_prefix, &sh_rem, shift);
        if (tid < 256) hist[tid] = 0;
        if (p == 3 && tid == 0) { cgt = 0; ceq = 0; }
        __syncthreads();
    }
    unsigned T = sh_prefix;
    int nEq = sh_rem;
    int nGt = TOPK - nEq;

    float* outS = g_cand_score + blk * TOPK;
    int*   outV = g_cand_vox   + blk * TOPK;
    int voff = chunk * CHUNK;
    for (int v = tid; v < CHUNK; v += nt) {
        unsigned k = skey[v];
        int slot = -1;
        if (k > T)       slot = atomicAdd(&cgt, 1);
        else if (k == T) { int q = atomicAdd(&ceq, 1); if (q < nEq) slot = nGt + q; }
        if (slot >= 0) { outS[slot] = src[v]; outV[slot] = voff + v; }
    }
}

// ---------------- kernel 3: per-batch top-500 of 20000 (rank-by-count) ----------------
__global__ void global_topk_kernel() {
    extern __shared__ unsigned sm3[];
    unsigned* skey = sm3;                                                // [20000]
    unsigned long long* sortb = (unsigned long long*)(sm3 + CAND_PER_B); // [512]
    __shared__ int hist[256];
    __shared__ unsigned sh_prefix;
    __shared__ int sh_rem, cgt, ceq;

    int b = blockIdx.x, tid = threadIdx.x, nt = blockDim.x;
    const float* cs = g_cand_score + (long)b * CAND_PER_B;

    for (int i = tid; i < CAND_PER_B; i += nt) skey[i] = key_of(cs[i]);
    if (tid < 512) sortb[tid] = 0ull;
    if (tid == 0) { sh_prefix = 0; sh_rem = TOPK; }
    if (tid < 256) hist[tid] = 0;
    __syncthreads();

    #pragma unroll
    for (int p = 0; p < 4; p++) {
        int shift = 24 - 8*p;
        unsigned mask = c_mask[p], pref = sh_prefix;
        for (int i = tid; i < CAND_PER_B; i += nt) {
            unsigned k = skey[i];
            hist_add(hist, (k >> shift) & 0xFF, (k & mask) == pref);
        }
        pick_bucket(hist, &sh_prefix, &sh_rem, shift);
        if (tid < 256) hist[tid] = 0;
        if (p == 3 && tid == 0) { cgt = 0; ceq = 0; }
        __syncthreads();
    }
    unsigned T = sh_prefix;
    int nEq = sh_rem;
    int nGt = TOPK - nEq;

    for (int i = tid; i < CAND_PER_B; i += nt) {
        unsigned k = skey[i];
        int slot = -1;
        if (k > T)       slot = atomicAdd(&cgt, 1);
        else if (k == T) { int q = atomicAdd(&ceq, 1); if (q < nEq) slot = nGt + q; }
        if (slot >= 0)
            sortb[slot] = (((unsigned long long)k) << 32) | (unsigned)i;
    }
    __syncthreads();

    if (tid < 512) {
        unsigned long long mine = sortb[tid];
        int rank = 0;
        for (int j = 0; j < 512; j++)
            rank += (sortb[j] > mine);
        if (mine != 0ull && rank < TOPK) {
            int idx = (int)(mine & 0xFFFFFFFFu);
            g_sel_score[b*TOPK + rank] = float_of((unsigned)(mine >> 32));
            g_sel_cls  [b*TOPK + rank] = idx / (NCHUNK*TOPK);
            g_sel_vox  [b*TOPK + rank] = g_cand_vox[(long)b*CAND_PER_B + idx];
        }
    }
}

// ---------------- kernel 4a: one (cand-group, head) per 128-thread block ----------------
__global__ void __launch_bounds__(128)
head_kernel(const float* __restrict__ feats,
            const float* __restrict__ W1, const float* __restrict__ b1,
            const float* __restrict__ gam, const float* __restrict__ bet,
            const float* __restrict__ mu,  const float* __restrict__ var,
            const float* __restrict__ W2c, const float* __restrict__ b2c,
            const float* __restrict__ W2z, const float* __restrict__ b2z,
            const float* __restrict__ W2d, const float* __restrict__ b2d,
            const float* __restrict__ W2r, const float* __restrict__ b2r,
            const float* __restrict__ W2v, const float* __restrict__ b2v) {
    int hh  = blockIdx.x / NGRP;       // 0..4 (same-head blocks adjacent -> L2-hot W1)
    int grp = blockIdx.x % NGRP;
    int e0  = grp * GD_BATCH;
    int wt  = threadIdx.x;
    __shared__ __align__(16) float xr[GD_BATCH][C];
    __shared__ __align__(16) float hs[GD_BATCH][C];
    __shared__ int svox[GD_BATCH];

    if (wt < GD_BATCH) svox[wt] = g_sel_vox[e0 + wt];
    __syncthreads();

    #pragma unroll
    for (int c = 0; c < GD_BATCH; c++) {
        int e = e0 + c;
        int row = (e / TOPK) * NVOX + svox[c];
        xr[c][wt] = __ldg(feats + (long)row*C + wt);
    }
    __syncthreads();

    const float* w2; const float* bp2; int oc, sb;
    if      (hh == 0) { w2 = W2c; bp2 = b2c; oc = 2; sb = 0; }
    else if (hh == 1) { w2 = W2z; bp2 = b2z; oc = 1; sb = 2; }
    else if (hh == 2) { w2 = W2d; bp2 = b2d; oc = 3; sb = 3; }
    else if (hh == 3) { w2 = W2r; bp2 = b2r; oc = 2; sb = 6; }
    else              { w2 = W2v; bp2 = b2v; oc = 2; sb = 8; }

    // first layer: channel wt for all 8 candidates; k vectorized by 4
    {
        int h = hh + 1;
        int hc = h*C + wt;
        float inv = gam[hc] / sqrtf(var[hc] + 1e-5f);
        float bb  = (b1[hc] - mu[hc]) * inv + bet[hc];
        const float* w = W1 + h*C*C + wt;
        float acc[GD_BATCH];
        #pragma unroll
        for (int c = 0; c < GD_BATCH; c++) acc[c] = 0.f;
        #pragma unroll 4
        for (int k4 = 0; k4 < C/4; k4++) {
            int kk = k4 * 4;
            float w0 = __ldg(w + (kk+0)*C);
            float w1v = __ldg(w + (kk+1)*C);
            float w2v = __ldg(w + (kk+2)*C);
            float w3 = __ldg(w + (kk+3)*C);
            #pragma unroll
            for (int c = 0; c < GD_BATCH; c++) {
                float4 xv = *reinterpret_cast<const float4*>(&xr[c][kk]);
                acc[c] += xv.x*w0 + xv.y*w1v + xv.z*w2v + xv.w*w3;
            }
        }
        #pragma unroll
        for (int c = 0; c < GD_BATCH; c++) hs[c][wt] = fmaxf(acc[c]*inv + bb, 0.f);
    }
    __syncthreads();

    // second layer: k-parallel, 16 lanes per candidate
    {
        int cand = wt >> 4, ln = wt & 15;
        float pc[3] = {0.f, 0.f, 0.f};
        #pragma unroll
        for (int q = 0; q < 8; q++) {
            int kk = ln + q*16;
            float hv = hs[cand][kk];
            #pragma unroll
            for (int col = 0; col < 3; col++)
                if (col < oc) pc[col] += hv * __ldg(w2 + kk*oc + col);
        }
        #pragma unroll
        for (int col = 0; col < 3; col++) {
            float v = pc[col];
            v += __shfl_xor_sync(0xffffffff, v, 1);
            v += __shfl_xor_sync(0xffffffff, v, 2);
            v += __shfl_xor_sync(0xffffffff, v, 4);
            v += __shfl_xor_sync(0xffffffff, v, 8);
            pc[col] = v;
        }
        if (ln == 0) {
            int e = e0 + cand;
            #pragma unroll
            for (int col = 0; col < 3; col++)
                if (col < oc) {
                    float a2 = pc[col] + __ldg(bp2 + col);
                    g_res[e*10 + sb + col] = (hh == 2) ? expf(a2) : a2;
                }
        }
    }
}

// ---------------- kernel 4b: per-candidate decode ----------------
__global__ void __launch_bounds__(256)
decode_kernel(const int* __restrict__ voxel_xy, float* __restrict__ out) {
    int e = blockIdx.x * 256 + threadIdx.x;
    if (e >= BATCH*TOPK) return;
    int b = e / TOPK, k = e % TOPK;
    float score = 1.f / (1.f + expf(-g_sel_score[e]));
    int   cls   = g_sel_cls[e];
    int   vox   = g_sel_vox[e];
    int   row   = b * NVOX + vox;
    const float* r = g_res + e*10;
    float vx = (float)voxel_xy[row*2 + 0];
    float vy = (float)voxel_xy[row*2 + 1];
    float xs = (vx + r[0]) * 0.6f - 54.0f;
    float ys = (vy + r[1]) * 0.6f - 54.0f;
    float cz = r[2];
    float ang = atan2f(r[7], r[6]);
    bool m = (xs >= -61.2f) && (xs <= 61.2f) &&
             (ys >= -61.2f) && (ys <= 61.2f) &&
             (cz >= -10.f)  && (cz <= 10.f)  && (score > 0.1f);
    float mf = m ? 1.f : 0.f;
    float* ob = out + (long)(b*TOPK + k) * 10;
    ob[0] = xs * mf;  ob[1] = ys * mf;  ob[2] = cz * mf;
    ob[3] = r[3] * mf; ob[4] = r[4] * mf; ob[5] = r[5] * mf;
    ob[6] = ang * mf; ob[7] = r[8] * mf; ob[8] = r[9] * mf;
    ob[9] = score * mf;
    int base = b*TOPK + k;
    out[BATCH*TOPK*10                 + base] = m ? (float)(cls + 1) : 0.f;
    out[BATCH*TOPK*10 + BATCH*TOPK   + base] = (float)(vox + b*NVOX);
    out[BATCH*TOPK*10 + 2*BATCH*TOPK + base] = mf;
}

// ---------------- host launcher ----------------
extern "C" void kernel_launch(void* const* d_in, const int* in_sizes, int n_in,
                              void* d_out, int out_size) {
    const float* feats    = (const float*)d_in[0];
    const int*   voxel_xy = (const int*)d_in[1];
    const float* W1  = (const float*)d_in[2];
    const float* b1  = (const float*)d_in[3];
    const float* gam = (const float*)d_in[4];
    const float* bet = (const float*)d_in[5];
    const float* mu  = (const float*)d_in[6];
    const float* var = (const float*)d_in[7];
    const float* W2_hm = (const float*)d_in[8];
    const float* b2_hm = (const float*)d_in[9];
    const float* W2_c  = (const float*)d_in[10];
    const float* b2_c  = (const float*)d_in[11];
    const float* W2_z  = (const float*)d_in[12];
    const float* b2_z  = (const float*)d_in[13];
    const float* W2_d  = (const float*)d_in[14];
    const float* b2_d  = (const float*)d_in[15];
    const float* W2_r  = (const float*)d_in[16];
    const float* b2_r  = (const float*)d_in[17];
    const float* W2_v  = (const float*)d_in[18];
    const float* b2_v  = (const float*)d_in[19];
    float* out = (float*)d_out;

    const int smem1 = SM_FLOATS * (int)sizeof(float);                 // 111104 B
    const int smem3 = CAND_PER_B * (int)sizeof(unsigned) + 512 * 8;
    cudaFuncSetAttribute(hm_kernel,          cudaFuncAttributeMaxDynamicSharedMemorySize, smem1);
    cudaFuncSetAttribute(global_topk_kernel, cudaFuncAttributeMaxDynamicSharedMemorySize, smem3);

    hm_kernel<<<HM_GRID, 256, smem1>>>(feats, W1, b1, gam, bet, mu, var, W2_hm, b2_hm);
    topk_chunk_kernel<<<BATCH * NCLS * NCHUNK, 512>>>();
    global_topk_kernel<<<BATCH, 1024, smem3>>>();
    head_kernel<<<5 * NGRP, 128>>>(feats, W1, b1, gam, bet, mu, var,
                                   W2_c, b2_c, W2_z, b2_z, W2_d, b2_d,
                                   W2_r, b2_r, W2_v, b2_v);
    decode_kernel<<<(BATCH*TOPK + 255)/256, 256>>>(voxel_xy, out);
}

// round 17
// speedup vs baseline: 1.3762x; 1.0466x over previous
#include <cuda_runtime.h>
#include <cuda_fp16.h>
#include <cstdint>

#define BATCH 4
#define NVOX  32768
#define NROWS (BATCH*NVOX)
#define C     128
#define NCLS  10
#define TOPK  500
#define NCHUNK 4
#define CHUNK  (NVOX/NCHUNK)          // 8192
#define CAND_PER_B (NCLS*NCHUNK*TOPK) // 20000
#define GD_BATCH 8
#define NGRP    (BATCH*TOPK/GD_BATCH) // 250

// hm mma.sync config: 64-row tiles, 256 threads / 8 warps (4 row-groups x 2 col-halves)
#define TROWS   64
#define HM_GRID 296
#define NTILES  (NROWS/TROWS)         // 2048
#define SM_HI  0
#define SM_LO  4352
#define SM_WP  8704
#define SM_W2  25088
#define SM_BF  26368
#define SM_PO  26496
#define SM_FLOATS 27776               // -> 111104 bytes (2 blocks/SM)

// ---------------- device scratch ----------------
__device__ float g_hm[BATCH*NCLS*NVOX];            // raw logits
__device__ float g_cand_score[BATCH*CAND_PER_B];
__device__ int   g_cand_vox[BATCH*CAND_PER_B];
__device__ float g_sel_score[BATCH*TOPK];
__device__ int   g_sel_cls[BATCH*TOPK];
__device__ int   g_sel_vox[BATCH*TOPK];
__device__ float g_res[BATCH*TOPK*10];             // head outputs per candidate

__device__ __forceinline__ void mma_f16(float* d, const uint32_t* a, uint32_t b0, uint32_t b1) {
    asm volatile("mma.sync.aligned.m16n8k16.row.col.f32.f16.f16.f32 "
        "{%0,%1,%2,%3}, {%4,%5,%6,%7}, {%8,%9}, {%0,%1,%2,%3};"
        : "+f"(d[0]), "+f"(d[1]), "+f"(d[2]), "+f"(d[3])
        : "r"(a[0]), "r"(a[1]), "r"(a[2]), "r"(a[3]), "r"(b0), "r"(b1));
}
__device__ __forceinline__ void ldmatrix_x4(uint32_t* r, uint32_t addr) {
    asm volatile("ldmatrix.sync.aligned.m8n8.x4.shared.b16 {%0,%1,%2,%3}, [%4];"
        : "=r"(r[0]), "=r"(r[1]), "=r"(r[2]), "=r"(r[3]) : "r"(addr));
}
__device__ __forceinline__ void split_pack(float x, float y, uint32_t& hi, uint32_t& lo) {
    __half2 h = __floats2half2_rn(x, y);
    float2 hf = __half22float2(h);
    __half2 l = __floats2half2_rn(x - hf.x, y - hf.y);
    hi = *reinterpret_cast<uint32_t*>(&h);
    lo = *reinterpret_cast<uint32_t*>(&l);
}

// ---------------- kernel 1: dense hm head, fp16 split + ldmatrix A planes ----------------
__global__ void __launch_bounds__(256, 2)
hm_kernel(const float* __restrict__ feats,
          const float* __restrict__ W1, const float* __restrict__ b1,
          const float* __restrict__ gam, const float* __restrict__ bet,
          const float* __restrict__ mu,  const float* __restrict__ var,
          const float* __restrict__ W2, const float* __restrict__ b2) {
    extern __shared__ float sm[];
    uint32_t* hip = reinterpret_cast<uint32_t*>(sm) + SM_HI;   // [64][68]
    uint32_t* lop = reinterpret_cast<uint32_t*>(sm) + SM_LO;
    float*  Wp  = sm + SM_WP;
    float4* Wp4 = reinterpret_cast<float4*>(Wp);
    float*  W2s = sm + SM_W2;
    float*  bfs = sm + SM_BF;
    float*  po2 = sm + SM_PO;              // [2][64][10]; inv[] during prologue

    int tid  = threadIdx.x;
    int lane = tid & 31;
    int wid  = tid >> 5;
    int wm = wid >> 1, wn = wid & 1;       // warp tile: rows wm*16, cols wn*64

    uint32_t smbase = (uint32_t)__cvta_generic_to_shared(sm);

    // ---- prologue: fold BN for head 0, pack fp16 hi/lo fragments ----
    if (tid < C) {
        float inv = gam[tid] / sqrtf(var[tid] + 1e-5f);
        po2[tid] = inv;
        bfs[tid] = (b1[tid] - mu[tid]) * inv + bet[tid];
    }
    for (int i = tid; i < C*NCLS; i += 256) W2s[i] = W2[i];
    __syncthreads();
    for (int i = tid; i < C*C/2; i += 256) {
        int c  = i & 127;
        int kp = i >> 7;                 // 0..63
        int k0 = kp * 2;
        float inv = po2[c];
        float v0 = W1[k0*C + c] * inv;
        float v1 = W1[(k0+1)*C + c] * inv;
        uint32_t hi, lo;
        split_pack(v0, v1, hi, lo);
        int kk  = k0 & 15;               // even
        int reg = (kk < 8) ? 0 : 1;
        int tig = (kk & 7) >> 1;
        int ks  = k0 >> 4;
        int nt  = c >> 3;
        int ln  = ((c & 7) << 2) | tig;
        int base = (((ks*16) + nt)*32 + ln) * 4;
        Wp[base + reg]     = __uint_as_float(hi);
        Wp[base + 2 + reg] = __uint_as_float(lo);
    }
    float b2r[NCLS];
    #pragma unroll
    for (int j = 0; j < NCLS; j++) b2r[j] = __ldg(b2 + j);

    // per-lane ldmatrix addresses (hi plane; lo = +SM_LO words)
    int grp  = lane >> 3;
    int lrow = wm*16 + (lane & 7) + ((grp & 1) << 3);
    int kboff = (grp >> 1) * 4;                       // uint32 words
    uint32_t a_hi0 = smbase + (uint32_t)(SM_HI + lrow*68 + kboff) * 4u;
    uint32_t a_lo0 = smbase + (uint32_t)(SM_LO + lrow*68 + kboff) * 4u;

    for (int tile = blockIdx.x; tile < NTILES; tile += HM_GRID) {
        int row0 = tile * TROWS;

        // ---- load + convert X tile into fp16 hi/lo planes ----
        for (int i = tid; i < TROWS*32; i += 256) {
            int r  = i >> 5;
            int c4 = (i & 31) << 2;
            float4 f = *reinterpret_cast<const float4*>(feats + (long)(row0 + r)*C + c4);
            uint32_t h0, l0, h1, l1;
            split_pack(f.x, f.y, h0, l0);
            split_pack(f.z, f.w, h1, l1);
            int w = r*68 + (c4 >> 1);
            *reinterpret_cast<uint2*>(&hip[w]) = make_uint2(h0, h1);
            *reinterpret_cast<uint2*>(&lop[w]) = make_uint2(l0, l1);
        }
        __syncthreads();        // planes ready; Wp ready (first iter)

        float acc[8][4];
        #pragma unroll
        for (int ni = 0; ni < 8; ni++)
            #pragma unroll
            for (int q = 0; q < 4; q++) acc[ni][q] = 0.f;

        #pragma unroll
        for (int ks = 0; ks < 8; ks++) {
            uint32_t ahi[4], alo[4];
            ldmatrix_x4(ahi, a_hi0 + (uint32_t)(ks*8)*4u);
            ldmatrix_x4(alo, a_lo0 + (uint32_t)(ks*8)*4u);
            #pragma unroll
            for (int ni = 0; ni < 8; ni++) {
                int nt = wn*8 + ni;
                float4 v = Wp4[(ks*16 + nt)*32 + lane];
                uint32_t bh0 = __float_as_uint(v.x), bh1 = __float_as_uint(v.y);
                uint32_t bl0 = __float_as_uint(v.z), bl1 = __float_as_uint(v.w);
                mma_f16(acc[ni], ahi, bh0, bh1);
                mma_f16(acc[ni], ahi, bl0, bl1);
                mma_f16(acc[ni], alo, bh0, bh1);
            }
        }
        __syncthreads();        // all warps done READING planes

        // ---- epilogue directly from accumulators ----
        float po[2][NCLS];
        #pragma unroll
        for (int s = 0; s < 2; s++)
            #pragma unroll
            for (int j = 0; j < NCLS; j++) po[s][j] = 0.f;

        #pragma unroll
        for (int ni = 0; ni < 8; ni++) {
            #pragma unroll
            for (int t = 0; t < 2; t++) {
                int c = wn*64 + ni*8 + 2*(lane & 3) + t;
                float bfc = bfs[c];
                float w2l[NCLS];
                #pragma unroll
                for (int j = 0; j < NCLS; j++) w2l[j] = W2s[c*NCLS + j];
                float h0 = fmaxf(acc[ni][t]     + bfc, 0.f);
                float h1 = fmaxf(acc[ni][t + 2] + bfc, 0.f);
                #pragma unroll
                for (int j = 0; j < NCLS; j++) {
                    po[0][j] += h0 * w2l[j];
                    po[1][j] += h1 * w2l[j];
                }
            }
        }
        #pragma unroll
        for (int s = 0; s < 2; s++)
            #pragma unroll
            for (int j = 0; j < NCLS; j++) {
                float v = po[s][j];
                v += __shfl_xor_sync(0xffffffff, v, 1);
                v += __shfl_xor_sync(0xffffffff, v, 2);
                po[s][j] = v;
            }
        if ((lane & 3) == 0) {
            int rbase = wm*16 + (lane >> 2);
            #pragma unroll
            for (int s = 0; s < 2; s++) {
                int row = rbase + s*8;
                #pragma unroll
                for (int j = 0; j < NCLS; j++)
                    po2[(wn*64 + row)*NCLS + j] = po[s][j];
            }
        }
        __syncthreads();

        if (tid < 128) {
            int row = tid >> 1;              // 0..63
            int j0  = (tid & 1) * 5;
            int rrow = row0 + row;
            int b    = rrow >> 15;
            int v    = rrow & (NVOX - 1);
            #pragma unroll
            for (int j = 0; j < 5; j++) {
                float val = po2[row*NCLS + j0 + j] + po2[(64 + row)*NCLS + j0 + j] + b2r[j0 + j];
                g_hm[((long)(b*NCLS + j0 + j))*NVOX + v] = val;
            }
        }
        __syncthreads();        // po2 read done; planes free for next conv
    }
}

// ---------------- radix helpers ----------------
__device__ __forceinline__ unsigned key_of(float f) {
    unsigned u = __float_as_uint(f);
    return (u & 0x80000000u) ? ~u : (u | 0x80000000u);
}
__device__ __forceinline__ float float_of(unsigned k) {
    unsigned u = (k & 0x80000000u) ? (k & 0x7FFFFFFFu) : ~k;
    return __uint_as_float(u);
}
__device__ __forceinline__ void hist_add(int* hist, unsigned bin, bool act) {
    unsigned lm = __activemask();
    unsigned amask = __ballot_sync(lm, act);
    if (act) {
        unsigned peers = __match_any_sync(amask, bin);
        int leader = __ffs(peers) - 1;
        if ((int)(threadIdx.x & 31) == leader)
            atomicAdd(&hist[bin], __popc(peers));
    }
}
__device__ __forceinline__ void pick_bucket(int* hist, unsigned* sh_prefix,
                                            int* sh_rem, int shift) {
    __syncthreads();
    if (threadIdx.x < 32) {
        int lane = threadIdx.x;
        int b0 = lane * 8;
        int loc[8];
        int tot = 0;
        #pragma unroll
        for (int q = 0; q < 8; q++) { loc[q] = hist[b0 + q]; tot += loc[q]; }
        int s = tot;
        #pragma unroll
        for (int off = 1; off < 32; off <<= 1) {
            int t = __shfl_down_sync(0xffffffff, s, off);
            if (lane + off < 32) s += t;
        }
        int rem = *sh_rem;
        int cum = s - tot;
        #pragma unroll
        for (int q = 7; q >= 0; q--) {
            int prev = cum;
            cum += loc[q];
            if (cum >= rem && prev < rem) {
                *sh_rem    = rem - prev;
                *sh_prefix = *sh_prefix | ((unsigned)(b0 + q) << shift);
            }
        }
    }
    __syncthreads();
}
__constant__ unsigned c_mask[4] = {0u, 0xFF000000u, 0xFFFF0000u, 0xFFFFFF00u};

// ---------------- kernel 2: per-(b,cls,chunk) local top-500, register-resident ----------------
#define CQ 16    // keys per thread (512 threads * 16 = 8192)
__global__ void __launch_bounds__(512)
topk_chunk_kernel() {
    __shared__ int hist[256];
    __shared__ unsigned sh_prefix;
    __shared__ int sh_rem, cgt, ceq;

    int blk = blockIdx.x;
    int bc  = blk >> 2, chunk = blk & 3;
    int tid = threadIdx.x;
    const float* src = g_hm + (long)bc * NVOX + chunk * CHUNK;

    unsigned key[CQ];
    #pragma unroll
    for (int q = 0; q < CQ; q++) key[q] = key_of(src[tid + q*512]);
    if (tid == 0) { sh_prefix = 0; sh_rem = TOPK; }
    if (tid < 256) hist[tid] = 0;
    __syncthreads();

    #pragma unroll
    for (int p = 0; p < 4; p++) {
        int shift = 24 - 8*p;
        unsigned mask = c_mask[p], pref = sh_prefix;
        #pragma unroll
        for (int q = 0; q < CQ; q++)
            hist_add(hist, (key[q] >> shift) & 0xFF, (key[q] & mask) == pref);
        pick_bucket(hist, &sh_prefix, &sh_rem, shift);
        if (tid < 256) hist[tid] = 0;
        if (p == 3 && tid == 0) { cgt = 0; ceq = 0; }
        __syncthreads();
    }
    unsigned T = sh_prefix;
    int nEq = sh_rem;
    int nGt = TOPK - nEq;

    float* outS = g_cand_score + blk * TOPK;
    int*   outV = g_cand_vox   + blk * TOPK;
    int voff = chunk * CHUNK;
    #pragma unroll
    for (int q = 0; q < CQ; q++) {
        unsigned k = key[q];
        int slot = -1;
        if (k > T)       slot = atomicAdd(&cgt, 1);
        else if (k == T) { int qq = atomicAdd(&ceq, 1); if (qq < nEq) slot = nGt + qq; }
        if (slot >= 0) { outS[slot] = float_of(k); outV[slot] = voff + tid + q*512; }
    }
}

// ---------------- kernel 3: per-batch top-500 of 20000, register-resident ----------------
#define GQ 20    // keys per thread (1024 threads * 20 = 20480 >= 20000)
__global__ void __launch_bounds__(1024)
global_topk_kernel() {
    __shared__ unsigned long long sortb[512];
    __shared__ int hist[256];
    __shared__ unsigned sh_prefix;
    __shared__ int sh_rem, cgt, ceq;

    int b = blockIdx.x, tid = threadIdx.x;
    const float* cs = g_cand_score + (long)b * CAND_PER_B;

    unsigned key[GQ];
    #pragma unroll
    for (int q = 0; q < GQ; q++) {
        int i = tid + q*1024;
        key[q] = (i < CAND_PER_B) ? key_of(cs[i]) : 0u;   // key 0 = smallest
    }
    if (tid < 512) sortb[tid] = 0ull;
    if (tid == 0) { sh_prefix = 0; sh_rem = TOPK; }
    if (tid < 256) hist[tid] = 0;
    __syncthreads();

    #pragma unroll
    for (int p = 0; p < 4; p++) {
        int shift = 24 - 8*p;
        unsigned mask = c_mask[p], pref = sh_prefix;
        #pragma unroll
        for (int q = 0; q < GQ; q++) {
            int i = tid + q*1024;
            hist_add(hist, (key[q] >> shift) & 0xFF,
                     (i < CAND_PER_B) && ((key[q] & mask) == pref));
        }
        pick_bucket(hist, &sh_prefix, &sh_rem, shift);
        if (tid < 256) hist[tid] = 0;
        if (p == 3 && tid == 0) { cgt = 0; ceq = 0; }
        __syncthreads();
    }
    unsigned T = sh_prefix;
    int nEq = sh_rem;
    int nGt = TOPK - nEq;

    #pragma unroll
    for (int q = 0; q < GQ; q++) {
        int i = tid + q*1024;
        if (i >= CAND_PER_B) continue;
        unsigned k = key[q];
        int slot = -1;
        if (k > T)       slot = atomicAdd(&cgt, 1);
        else if (k == T) { int qq = atomicAdd(&ceq, 1); if (qq < nEq) slot = nGt + qq; }
        if (slot >= 0)
            sortb[slot] = (((unsigned long long)k) << 32) | (unsigned)i;
    }
    __syncthreads();

    if (tid < 512) {
        unsigned long long mine = sortb[tid];
        int rank = 0;
        for (int j = 0; j < 512; j++)
            rank += (sortb[j] > mine);
        if (mine != 0ull && rank < TOPK) {
            int idx = (int)(mine & 0xFFFFFFFFu);
            g_sel_score[b*TOPK + rank] = float_of((unsigned)(mine >> 32));
            g_sel_cls  [b*TOPK + rank] = idx / (NCHUNK*TOPK);
            g_sel_vox  [b*TOPK + rank] = g_cand_vox[(long)b*CAND_PER_B + idx];
        }
    }
}

// ---------------- kernel 4a: one (cand-group, head) per 128-thread block ----------------
__global__ void __launch_bounds__(128)
head_kernel(const float* __restrict__ feats,
            const float* __restrict__ W1, const float* __restrict__ b1,
            const float* __restrict__ gam, const float* __restrict__ bet,
            const float* __restrict__ mu,  const float* __restrict__ var,
            const float* __restrict__ W2c, const float* __restrict__ b2c,
            const float* __restrict__ W2z, const float* __restrict__ b2z,
            const float* __restrict__ W2d, const float* __restrict__ b2d,
            const float* __restrict__ W2r, const float* __restrict__ b2r,
            const float* __restrict__ W2v, const float* __restrict__ b2v) {
    int hh  = blockIdx.x / NGRP;
    int grp = blockIdx.x % NGRP;
    int e0  = grp * GD_BATCH;
    int wt  = threadIdx.x;
    __shared__ __align__(16) float xr[GD_BATCH][C];
    __shared__ __align__(16) float hs[GD_BATCH][C];
    __shared__ int svox[GD_BATCH];

    if (wt < GD_BATCH) svox[wt] = g_sel_vox[e0 + wt];
    __syncthreads();

    #pragma unroll
    for (int c = 0; c < GD_BATCH; c++) {
        int e = e0 + c;
        int row = (e / TOPK) * NVOX + svox[c];
        xr[c][wt] = __ldg(feats + (long)row*C + wt);
    }
    __syncthreads();

    const float* w2; const float* bp2; int oc, sb;
    if      (hh == 0) { w2 = W2c; bp2 = b2c; oc = 2; sb = 0; }
    else if (hh == 1) { w2 = W2z; bp2 = b2z; oc = 1; sb = 2; }
    else if (hh == 2) { w2 = W2d; bp2 = b2d; oc = 3; sb = 3; }
    else if (hh == 3) { w2 = W2r; bp2 = b2r; oc = 2; sb = 6; }
    else              { w2 = W2v; bp2 = b2v; oc = 2; sb = 8; }

    {
        int h = hh + 1;
        int hc = h*C + wt;
        float inv = gam[hc] / sqrtf(var[hc] + 1e-5f);
        float bb  = (b1[hc] - mu[hc]) * inv + bet[hc];
        const float* w = W1 + h*C*C + wt;
        float acc[GD_BATCH];
        #pragma unroll
        for (int c = 0; c < GD_BATCH; c++) acc[c] = 0.f;
        #pragma unroll 4
        for (int k4 = 0; k4 < C/4; k4++) {
            int kk = k4 * 4;
            float w0 = __ldg(w + (kk+0)*C);
            float w1v = __ldg(w + (kk+1)*C);
            float w2v = __ldg(w + (kk+2)*C);
            float w3 = __ldg(w + (kk+3)*C);
            #pragma unroll
            for (int c = 0; c < GD_BATCH; c++) {
                float4 xv = *reinterpret_cast<const float4*>(&xr[c][kk]);
                acc[c] += xv.x*w0 + xv.y*w1v + xv.z*w2v + xv.w*w3;
            }
        }
        #pragma unroll
        for (int c = 0; c < GD_BATCH; c++) hs[c][wt] = fmaxf(acc[c]*inv + bb, 0.f);
    }
    __syncthreads();

    {
        int cand = wt >> 4, ln = wt & 15;
        float pc[3] = {0.f, 0.f, 0.f};
        #pragma unroll
        for (int q = 0; q < 8; q++) {
            int kk = ln + q*16;
            float hv = hs[cand][kk];
            #pragma unroll
            for (int col = 0; col < 3; col++)
                if (col < oc) pc[col] += hv * __ldg(w2 + kk*oc + col);
        }
        #pragma unroll
        for (int col = 0; col < 3; col++) {
            float v = pc[col];
            v += __shfl_xor_sync(0xffffffff, v, 1);
            v += __shfl_xor_sync(0xffffffff, v, 2);
            v += __shfl_xor_sync(0xffffffff, v, 4);
            v += __shfl_xor_sync(0xffffffff, v, 8);
            pc[col] = v;
        }
        if (ln == 0) {
            int e = e0 + cand;
            #pragma unroll
            for (int col = 0; col < 3; col++)
                if (col < oc) {
                    float a2 = pc[col] + __ldg(bp2 + col);
                    g_res[e*10 + sb + col] = (hh == 2) ? expf(a2) : a2;
                }
        }
    }
}

// ---------------- kernel 4b: per-candidate decode ----------------
__global__ void __launch_bounds__(256)
decode_kernel(const int* __restrict__ voxel_xy, float* __restrict__ out) {
    int e = blockIdx.x * 256 + threadIdx.x;
    if (e >= BATCH*TOPK) return;
    int b = e / TOPK, k = e % TOPK;
    float score = 1.f / (1.f + expf(-g_sel_score[e]));
    int   cls   = g_sel_cls[e];
    int   vox   = g_sel_vox[e];
    int   row   = b * NVOX + vox;
    const float* r = g_res + e*10;
    float vx = (float)voxel_xy[row*2 + 0];
    float vy = (float)voxel_xy[row*2 + 1];
    float xs = (vx + r[0]) * 0.6f - 54.0f;
    float ys = (vy + r[1]) * 0.6f - 54.0f;
    float cz = r[2];
    float ang = atan2f(r[7], r[6]);
    bool m = (xs >= -61.2f) && (xs <= 61.2f) &&
             (ys >= -61.2f) && (ys <= 61.2f) &&
             (cz >= -10.f)  && (cz <= 10.f)  && (score > 0.1f);
    float mf = m ? 1.f : 0.f;
    float* ob = out + (long)(b*TOPK + k) * 10;
    ob[0] = xs * mf;  ob[1] = ys * mf;  ob[2] = cz * mf;
    ob[3] = r[3] * mf; ob[4] = r[4] * mf; ob[5] = r[5] * mf;
    ob[6] = ang * mf; ob[7] = r[8] * mf; ob[8] = r[9] * mf;
    ob[9] = score * mf;
    int base = b*TOPK + k;
    out[BATCH*TOPK*10                 + base] = m ? (float)(cls + 1) : 0.f;
    out[BATCH*TOPK*10 + BATCH*TOPK   + base] = (float)(vox + b*NVOX);
    out[BATCH*TOPK*10 + 2*BATCH*TOPK + base] = mf;
}

// ---------------- host launcher ----------------
extern "C" void kernel_launch(void* const* d_in, const int* in_sizes, int n_in,
                              void* d_out, int out_size) {
    const float* feats    = (const float*)d_in[0];
    const int*   voxel_xy = (const int*)d_in[1];
    const float* W1  = (const float*)d_in[2];
    const float* b1  = (const float*)d_in[3];
    const float* gam = (const float*)d_in[4];
    const float* bet = (const float*)d_in[5];
    const float* mu  = (const float*)d_in[6];
    const float* var = (const float*)d_in[7];
    const float* W2_hm = (const float*)d_in[8];
    const float* b2_hm = (const float*)d_in[9];
    const float* W2_c  = (const float*)d_in[10];
    const float* b2_c  = (const float*)d_in[11];
    const float* W2_z  = (const float*)d_in[12];
    const float* b2_z  = (const float*)d_in[13];
    const float* W2_d  = (const float*)d_in[14];
    const float* b2_d  = (const float*)d_in[15];
    const float* W2_r  = (const float*)d_in[16];
    const float* b2_r  = (const float*)d_in[17];
    const float* W2_v  = (const float*)d_in[18];
    const float* b2_v  = (const float*)d_in[19];
    float* out = (float*)d_out;

    const int smem1 = SM_FLOATS * (int)sizeof(float);                 // 111104 B
    cudaFuncSetAttribute(hm_kernel, cudaFuncAttributeMaxDynamicSharedMemorySize, smem1);

    hm_kernel<<<HM_GRID, 256, smem1>>>(feats, W1, b1, gam, bet, mu, var, W2_hm, b2_hm);
    topk_chunk_kernel<<<BATCH * NCLS * NCHUNK, 512>>>();
    global_topk_kernel<<<BATCH, 1024>>>();
    head_kernel<<<5 * NGRP, 128>>>(feats, W1, b1, gam, bet, mu, var,
                                   W2_c, b2_c, W2_z, b2_z, W2_d, b2_d,
                                   W2_r, b2_r, W2_v, b2_v);
    decode_kernel<<<(BATCH*TOPK + 255)/256, 256>>>(voxel_xy, out);
}